// round 12
// baseline (speedup 1.0000x reference)
#include <cuda_runtime.h>
#include <cuda_bf16.h>
#include <mma.h>
#include <cstdint>

using namespace nvcuda;

#define NN 60000
#define EE 600000
#define DD 128
#define SLOPE 0.01f
#define BB 256            // build blocks (co-resident @ 2/SM)
#define BT 1024           // build threads
#define NBLK 7500         // agg stats partial blocks (60000/8)
#define GEMM_GRID 296     // persistent GEMM: 2 CTAs/SM

typedef unsigned long long ull;

// ---------------- device scratch (static, no allocation) ----------------
__device__ int   g_is64;
__device__ int   g_cnt[NN];
__device__ int   g_part[BB];
__device__ int   g_rowstart[NN + 1];
__device__ int   g_next[NN];
__device__ int2  g_edge[EE];
__device__ float g_dinv[NN];
__device__ float g_xw[(size_t)NN * DD];
__device__ float g_h[(size_t)NN * DD];
__device__ float g_psum[(size_t)NBLK * DD];
__device__ float g_psq[(size_t)NBLK * DD];
__device__ float g_scale[DD];
__device__ float g_shift[DD];
__device__ unsigned g_barcnt;
__device__ unsigned g_epoch;
// W as bf16 hi/lo, row-major [k][n]: [layer][hi/lo][128*128]
__device__ __align__(16) __nv_bfloat16 g_wb[3][2][16384];

// ---------------- global spin barrier (BB blocks resident) -----------------
__device__ __forceinline__ void gsync() {
    __syncthreads();
    if (threadIdx.x == 0) {
        __threadfence();
        unsigned e = atomicAdd(&g_epoch, 0u);
        if (atomicAdd(&g_barcnt, 1u) == BB - 1u) {
            g_barcnt = 0u;
            __threadfence();
            atomicAdd(&g_epoch, 1u);
        } else {
            while (((volatile unsigned*)&g_epoch)[0] == e) { __nanosleep(64); }
        }
        __threadfence();
    }
    __syncthreads();
}

__device__ __forceinline__ int edge_at(const void* p, int idx, int is64) {
    return is64 ? ((const int*)p)[2 * idx] : ((const int*)p)[idx];
}

// ---------------- fused CSR build (1024 threads x 256 blocks, 2/SM) --------
__global__ __launch_bounds__(BT, 2) void k_build(const void* ei) {
    int t = threadIdx.x, b = blockIdx.x;
    int gid = b * BT + t;
    const int GSTR = BB * BT;

    if (gid == 0) {
        const long long* q = (const long long*)ei;
        int ok = 1;
        for (int j = 0; j < 256; j++) {
            long long v = q[j];
            if (v < 0 || v >= NN) { ok = 0; break; }
        }
        g_is64 = ok;
    }
    for (int i = gid; i < NN; i += GSTR) g_cnt[i] = 0;
    gsync();
    int is64 = g_is64;

    for (int e = gid; e < EE; e += GSTR) {
        int d = edge_at(ei, EE + e, is64);
        atomicAdd(&g_cnt[d], 1);
    }
    gsync();

    __shared__ int s[BT];
    __shared__ int sp[BB];
    int i = gid;
    int x = (i < NN) ? g_cnt[i] : 0;
    if (i < NN) g_dinv[i] = rsqrtf((float)(x + 1));
    s[t] = x;
    __syncthreads();
    for (int off = 1; off < BT; off <<= 1) {
        int v = (t >= off) ? s[t - off] : 0;
        __syncthreads();
        s[t] += v;
        __syncthreads();
    }
    int incl = s[t];
    if (t == BT - 1) g_part[b] = incl;
    gsync();

    if (t < BB) sp[t] = g_part[t];
    __syncthreads();
    for (int off = 1; off < BB; off <<= 1) {
        int v = 0;
        if (t < BB && t >= off) v = sp[t - off];
        __syncthreads();
        if (t < BB) sp[t] += v;
        __syncthreads();
    }
    int pre = (b > 0) ? sp[b - 1] : 0;
    if (i < NN) {
        int rs = pre + incl - x;
        g_rowstart[i] = rs;
        g_next[i] = rs;
    }
    if (gid == 0) g_rowstart[NN] = EE;
    gsync();

    for (int e = gid; e < EE; e += GSTR) {
        int sdx = edge_at(ei, e, is64);
        int dd  = edge_at(ei, EE + e, is64);
        int pos = atomicAdd(&g_next[dd], 1);
        g_edge[pos] = make_int2(sdx, __float_as_int(g_dinv[sdx]));
    }
}

// ---------------- W split to bf16 hi/lo (once per call) ----------------
__global__ void k_wconv(const float* __restrict__ w0, const float* __restrict__ w1,
                        const float* __restrict__ w2) {
    const float* W = (blockIdx.x == 0) ? w0 : ((blockIdx.x == 1) ? w1 : w2);
    __nv_bfloat16* d1 = g_wb[blockIdx.x][0];
    __nv_bfloat16* d2 = g_wb[blockIdx.x][1];
    for (int idx = threadIdx.x; idx < 16384; idx += 256) {
        float v = W[idx];
        __nv_bfloat16 h1 = __float2bfloat16(v);
        float r = v - __bfloat162float(h1);
        d1[idx] = h1;
        d2[idx] = __float2bfloat16(r);
    }
}

// ---------- persistent WMMA GEMM, 2 CTAs/SM for phase overlap --------------
// grid=296, 256 threads (8 warps: 4m x 2n of 16x64 warp tiles), 64-row tiles.
// B (hi/lo) staged once per CTA; A single-buffered — the co-resident CTA's
// MMA phase covers this CTA's load/stage/epilogue phases.
#define LDSR 136
#define B_ELEMS (128 * LDSR)     // 17408 bf16 per B buffer
#define A_ELEMS (64 * LDSR)      // 8704 bf16 per A buffer
#define SMEMSZ ((2 * B_ELEMS + 2 * A_ELEMS) * 2)   // 104448 bytes

__global__ __launch_bounds__(256, 2) void k_gemm_p(
    const float* __restrict__ A, int layer, float* __restrict__ C,
    int tile0, int ntiles, int use_bn, int act)
{
    extern __shared__ __nv_bfloat16 smb[];
    __nv_bfloat16* B1s = smb;
    __nv_bfloat16* B2s = smb + B_ELEMS;
    __nv_bfloat16* A1s = smb + 2 * B_ELEMS;
    __nv_bfloat16* A2s = A1s + A_ELEMS;

    int t = threadIdx.x, wid = t >> 5;
    int mo = (wid >> 1) * 16;      // warp row offset (4 m-warps x 16)
    int no = (wid & 1) * 64;       // warp col offset (2 n-warps x 64)
    int tend = tile0 + ntiles;

    // stage B hi/lo once (restride 128 -> 136)
    {
        const uint4* s1 = (const uint4*)g_wb[layer][0];
        const uint4* s2 = (const uint4*)g_wb[layer][1];
        for (int i = t; i < 2048; i += 256) {
            int row = (i * 8) >> 7, col = (i * 8) & 127;
            *(uint4*)&B1s[row * LDSR + col] = s1[i];
            *(uint4*)&B2s[row * LDSR + col] = s2[i];
        }
    }

    for (int tile = tile0 + blockIdx.x; tile < tend; tile += gridDim.x) {
        // load + split-stage A tile (64 x 128) with fused BN/act
        int r0 = tile * 64;
#pragma unroll
        for (int j = 0; j < 8; j++) {
            int i = t + j * 256;
            int row = i >> 5, col = (i & 31) * 4;
            int gr = r0 + row;
            float4 v = (gr < NN) ? *(const float4*)(A + (size_t)gr * DD + col)
                                 : make_float4(0.f, 0.f, 0.f, 0.f);
            if (use_bn) {
                v.x = v.x * g_scale[col + 0] + g_shift[col + 0];
                v.y = v.y * g_scale[col + 1] + g_shift[col + 1];
                v.z = v.z * g_scale[col + 2] + g_shift[col + 2];
                v.w = v.w * g_scale[col + 3] + g_shift[col + 3];
                if (act) {
                    v.x = v.x >= 0.f ? v.x : SLOPE * v.x;
                    v.y = v.y >= 0.f ? v.y : SLOPE * v.y;
                    v.z = v.z >= 0.f ? v.z : SLOPE * v.z;
                    v.w = v.w >= 0.f ? v.w : SLOPE * v.w;
                }
            }
            __nv_bfloat162 h1a = make_bfloat162(__float2bfloat16(v.x), __float2bfloat16(v.y));
            __nv_bfloat162 h1b = make_bfloat162(__float2bfloat16(v.z), __float2bfloat16(v.w));
            float rx = v.x - __bfloat162float(h1a.x);
            float ry = v.y - __bfloat162float(h1a.y);
            float rz = v.z - __bfloat162float(h1b.x);
            float rw = v.w - __bfloat162float(h1b.y);
            __nv_bfloat162 h2a = make_bfloat162(__float2bfloat16(rx), __float2bfloat16(ry));
            __nv_bfloat162 h2b = make_bfloat162(__float2bfloat16(rz), __float2bfloat16(rw));
            __nv_bfloat162* p1 = (__nv_bfloat162*)&A1s[row * LDSR + col];
            __nv_bfloat162* p2 = (__nv_bfloat162*)&A2s[row * LDSR + col];
            p1[0] = h1a; p1[1] = h1b;
            p2[0] = h2a; p2[1] = h2b;
        }
        __syncthreads();   // A (and, first iter, B) visible to all warps

        wmma::fragment<wmma::accumulator, 16, 16, 16, float> fc[4];
#pragma unroll
        for (int n = 0; n < 4; n++) wmma::fill_fragment(fc[n], 0.0f);

        for (int ks = 0; ks < 8; ks++) {
            wmma::fragment<wmma::matrix_a, 16, 16, 16, __nv_bfloat16,
                           wmma::row_major> fa1, fa2;
            wmma::load_matrix_sync(fa1, &A1s[mo * LDSR + ks * 16], LDSR);
            wmma::load_matrix_sync(fa2, &A2s[mo * LDSR + ks * 16], LDSR);
#pragma unroll
            for (int n = 0; n < 4; n++) {
                wmma::fragment<wmma::matrix_b, 16, 16, 16, __nv_bfloat16,
                               wmma::row_major> fb1, fb2;
                wmma::load_matrix_sync(fb1, &B1s[(ks * 16) * LDSR + no + n * 16], LDSR);
                wmma::load_matrix_sync(fb2, &B2s[(ks * 16) * LDSR + no + n * 16], LDSR);
                wmma::mma_sync(fc[n], fa1, fb1, fc[n]);
                wmma::mma_sync(fc[n], fa2, fb1, fc[n]);
                wmma::mma_sync(fc[n], fa1, fb2, fc[n]);
            }
        }

        int rb = r0 + mo;             // NN % 16 == 0: strip all-in/all-out
        if (rb + 16 <= NN) {
#pragma unroll
            for (int n = 0; n < 4; n++)
                wmma::store_matrix_sync(C + (size_t)rb * DD + no + n * 16,
                                        fc[n], DD, wmma::mem_row_major);
        }
        __syncthreads();   // compute done before next iteration restages A
    }
}

// ---- aggregation: warp/node CSR gather + store-based BN-stats partials ----
__global__ __launch_bounds__(256, 7) void k_agg(
    const float* __restrict__ xw, float* __restrict__ outp,
    float* __restrict__ psum, float* __restrict__ psq)
{
    __shared__ float s1[8][128], s2[8][128];
    int t = threadIdx.x;
    int wid = t >> 5, lane = t & 31;
    int w = blockIdx.x * 8 + wid;
    float di = g_dinv[w];

    float4 acc = __ldg(reinterpret_cast<const float4*>(xw + (size_t)w * DD) + lane);
    float cself = di * di;
    acc.x *= cself; acc.y *= cself; acc.z *= cself; acc.w *= cself;

    int beg = g_rowstart[w], end = g_rowstart[w + 1];
    int i = beg;
    for (; i + 3 < end; i += 4) {
        int2 e0 = __ldg(&g_edge[i + 0]);
        int2 e1 = __ldg(&g_edge[i + 1]);
        int2 e2 = __ldg(&g_edge[i + 2]);
        int2 e3 = __ldg(&g_edge[i + 3]);
        float4 v0 = __ldg(reinterpret_cast<const float4*>(xw + (size_t)e0.x * DD) + lane);
        float4 v1 = __ldg(reinterpret_cast<const float4*>(xw + (size_t)e1.x * DD) + lane);
        float4 v2 = __ldg(reinterpret_cast<const float4*>(xw + (size_t)e2.x * DD) + lane);
        float4 v3 = __ldg(reinterpret_cast<const float4*>(xw + (size_t)e3.x * DD) + lane);
        float c0 = di * __int_as_float(e0.y);
        float c1 = di * __int_as_float(e1.y);
        float c2 = di * __int_as_float(e2.y);
        float c3 = di * __int_as_float(e3.y);
        acc.x = fmaf(c0, v0.x, acc.x); acc.y = fmaf(c0, v0.y, acc.y);
        acc.z = fmaf(c0, v0.z, acc.z); acc.w = fmaf(c0, v0.w, acc.w);
        acc.x = fmaf(c1, v1.x, acc.x); acc.y = fmaf(c1, v1.y, acc.y);
        acc.z = fmaf(c1, v1.z, acc.z); acc.w = fmaf(c1, v1.w, acc.w);
        acc.x = fmaf(c2, v2.x, acc.x); acc.y = fmaf(c2, v2.y, acc.y);
        acc.z = fmaf(c2, v2.z, acc.z); acc.w = fmaf(c2, v2.w, acc.w);
        acc.x = fmaf(c3, v3.x, acc.x); acc.y = fmaf(c3, v3.y, acc.y);
        acc.z = fmaf(c3, v3.z, acc.z); acc.w = fmaf(c3, v3.w, acc.w);
    }
    if (i < end) {
        int last = end - 1;
        int2 e0 = __ldg(&g_edge[i]);
        int2 e1 = __ldg(&g_edge[min(i + 1, last)]);
        int2 e2 = __ldg(&g_edge[min(i + 2, last)]);
        float4 v0 = __ldg(reinterpret_cast<const float4*>(xw + (size_t)e0.x * DD) + lane);
        float4 v1 = __ldg(reinterpret_cast<const float4*>(xw + (size_t)e1.x * DD) + lane);
        float4 v2 = __ldg(reinterpret_cast<const float4*>(xw + (size_t)e2.x * DD) + lane);
        float c0 = di * __int_as_float(e0.y);
        float c1 = (i + 1 < end) ? di * __int_as_float(e1.y) : 0.f;
        float c2 = (i + 2 < end) ? di * __int_as_float(e2.y) : 0.f;
        acc.x = fmaf(c0, v0.x, acc.x); acc.y = fmaf(c0, v0.y, acc.y);
        acc.z = fmaf(c0, v0.z, acc.z); acc.w = fmaf(c0, v0.w, acc.w);
        acc.x = fmaf(c1, v1.x, acc.x); acc.y = fmaf(c1, v1.y, acc.y);
        acc.z = fmaf(c1, v1.z, acc.z); acc.w = fmaf(c1, v1.w, acc.w);
        acc.x = fmaf(c2, v2.x, acc.x); acc.y = fmaf(c2, v2.y, acc.y);
        acc.z = fmaf(c2, v2.z, acc.z); acc.w = fmaf(c2, v2.w, acc.w);
    }
    reinterpret_cast<float4*>(outp + (size_t)w * DD)[lane] = acc;

    reinterpret_cast<float4*>(&s1[wid][0])[lane] = acc;
    reinterpret_cast<float4*>(&s2[wid][0])[lane] =
        make_float4(acc.x * acc.x, acc.y * acc.y, acc.z * acc.z, acc.w * acc.w);
    __syncthreads();
    if (t < 128) {
        float a = 0.f, b = 0.f;
#pragma unroll
        for (int ww = 0; ww < 8; ww++) { a += s1[ww][t]; b += s2[ww][t]; }
        psum[(size_t)blockIdx.x * DD + t] = a;
        psq [(size_t)blockIdx.x * DD + t] = b;
    }
}

// ---------------- BN stats finalize: block per feature ----------------
__global__ __launch_bounds__(256) void k_stats2(
    const float* __restrict__ gw, const float* __restrict__ be)
{
    __shared__ double r1[256], r2[256];
    int d = blockIdx.x;
    double s = 0.0, q = 0.0;
    for (int b = threadIdx.x; b < NBLK; b += 256) {
        s += (double)g_psum[(size_t)b * DD + d];
        q += (double)g_psq [(size_t)b * DD + d];
    }
    r1[threadIdx.x] = s; r2[threadIdx.x] = q;
    __syncthreads();
    for (int off = 128; off > 0; off >>= 1) {
        if (threadIdx.x < off) {
            r1[threadIdx.x] += r1[threadIdx.x + off];
            r2[threadIdx.x] += r2[threadIdx.x + off];
        }
        __syncthreads();
    }
    if (threadIdx.x == 0) {
        double mu = r1[0] / (double)NN;
        double var = r2[0] / (double)NN - mu * mu;
        float inv = (float)(1.0 / sqrt(var + 1e-5));
        float scl = gw[d] * inv;
        g_scale[d] = scl;
        g_shift[d] = be[d] - (float)mu * scl;
    }
}

// ---------------- final BN apply ----------------
__global__ void k_apply(float* __restrict__ h) {
    int idx = blockIdx.x * blockDim.x + threadIdx.x;
    if (idx < NN * DD / 4) {
        float4 v = reinterpret_cast<float4*>(h)[idx];
        int d = (idx & 31) * 4;
        v.x = v.x * g_scale[d + 0] + g_shift[d + 0];
        v.y = v.y * g_scale[d + 1] + g_shift[d + 1];
        v.z = v.z * g_scale[d + 2] + g_shift[d + 2];
        v.w = v.w * g_scale[d + 3] + g_shift[d + 3];
        reinterpret_cast<float4*>(h)[idx] = v;
    }
}

// ---------------- host launcher ----------------
extern "C" void kernel_launch(void* const* d_in, const int* in_sizes, int n_in,
                              void* d_out, int out_size) {
    const float* x   = (const float*)d_in[0];
    const void*  ei  = d_in[1];
    const float* w0  = (const float*)d_in[2];
    const float* g0  = (const float*)d_in[4];
    const float* be0 = (const float*)d_in[5];
    const float* w1  = (const float*)d_in[6];
    const float* g1  = (const float*)d_in[8];
    const float* be1 = (const float*)d_in[9];
    const float* w2  = (const float*)d_in[10];
    const float* g2  = (const float*)d_in[12];
    const float* be2 = (const float*)d_in[13];
    float* out = (float*)d_out;

    float *xw, *h, *ps, *pq;
    cudaGetSymbolAddress((void**)&xw, g_xw);
    cudaGetSymbolAddress((void**)&h,  g_h);
    cudaGetSymbolAddress((void**)&ps, g_psum);
    cudaGetSymbolAddress((void**)&pq, g_psq);

    static int smem_set = 0;
    if (!smem_set) {
        cudaFuncSetAttribute(k_gemm_p, cudaFuncAttributeMaxDynamicSharedMemorySize, SMEMSZ);
        smem_set = 1;
    }

    const int TB = 256;
    const int GTILES = (NN + 63) / 64;     // 938
    const int GH = GTILES / 2;             // 469
    int gbP = (NN * DD / 4 + TB - 1) / TB;

    // layer 0 (launch #4 = GEMM second half -> ncu capture slot)
    k_build<<<BB, BT>>>(ei);                                               // 1
    k_wconv<<<3, TB>>>(w0, w1, w2);                                        // 2
    k_gemm_p<<<GEMM_GRID, TB, SMEMSZ>>>(x, 0, xw, 0, GH, 0, 0);            // 3
    k_gemm_p<<<GEMM_GRID, TB, SMEMSZ>>>(x, 0, xw, GH, GTILES - GH, 0, 0);  // 4 <- profiled
    k_agg<<<NBLK, TB>>>(xw, h, ps, pq);                                    // 5
    k_stats2<<<DD, TB>>>(g0, be0);                                         // 6

    // layer 1 (BN0 + LeakyReLU fused into A staging)
    k_gemm_p<<<GEMM_GRID, TB, SMEMSZ>>>(h, 1, xw, 0, GTILES, 1, 1);
    k_agg<<<NBLK, TB>>>(xw, h, ps, pq);
    k_stats2<<<DD, TB>>>(g1, be1);

    // layer 2 (BN1 + LeakyReLU fused), final BN standalone
    k_gemm_p<<<GEMM_GRID, TB, SMEMSZ>>>(h, 2, xw, 0, GTILES, 1, 1);
    k_agg<<<NBLK, TB>>>(xw, out, ps, pq);
    k_stats2<<<DD, TB>>>(g2, be2);
    k_apply<<<gbP, TB>>>(out);
}

// round 13
// speedup vs baseline: 1.1767x; 1.1767x over previous
#include <cuda_runtime.h>
#include <cuda_bf16.h>
#include <cstdint>

#define NN 60000
#define EE 600000
#define DD 128
#define SLOPE 0.01f
#define BB 256            // build blocks (co-resident @ 2/SM)
#define BT 1024           // build threads
#define NBLK 7500         // agg stats partial blocks (60000/8)
#define GEMM_GRID 296     // persistent GEMM: 2 CTAs/SM

typedef unsigned long long ull;

// ---------------- device scratch (static, no allocation) ----------------
__device__ int   g_is64;
__device__ int   g_cnt[NN];
__device__ int   g_part[BB];
__device__ int   g_rowstart[NN + 1];
__device__ int   g_next[NN];
__device__ int2  g_edge[EE];
__device__ float g_dinv[NN];
__device__ float g_xw[(size_t)NN * DD];
__device__ float g_h[(size_t)NN * DD];
__device__ float g_psum[(size_t)NBLK * DD];
__device__ float g_psq[(size_t)NBLK * DD];
__device__ float g_scale[DD];
__device__ float g_shift[DD];
__device__ unsigned g_barcnt;
__device__ unsigned g_epoch;
// W as bf16 hi/lo, row-major [k][n]: [layer][hi/lo][128*128]
__device__ __align__(16) __nv_bfloat16 g_wb[3][2][16384];

// ---------------- mma.sync / ldmatrix primitives ----------------
__device__ __forceinline__ uint32_t smem_u32(const void* p) {
    return (uint32_t)__cvta_generic_to_shared(p);
}
#define LDSM4(r, addr)                                                         \
    asm volatile("ldmatrix.sync.aligned.m8n8.x4.shared.b16 {%0,%1,%2,%3}, [%4];" \
                 : "=r"((r)[0]), "=r"((r)[1]), "=r"((r)[2]), "=r"((r)[3])      \
                 : "r"(addr))
#define LDSM4T(r, addr)                                                        \
    asm volatile("ldmatrix.sync.aligned.m8n8.x4.trans.shared.b16 {%0,%1,%2,%3}, [%4];" \
                 : "=r"((r)[0]), "=r"((r)[1]), "=r"((r)[2]), "=r"((r)[3])      \
                 : "r"(addr))
#define MMA16816(d, a, b0, b1)                                                 \
    asm volatile("mma.sync.aligned.m16n8k16.row.col.f32.bf16.bf16.f32 "        \
                 "{%0,%1,%2,%3},{%4,%5,%6,%7},{%8,%9},{%0,%1,%2,%3};"          \
                 : "+f"((d)[0]), "+f"((d)[1]), "+f"((d)[2]), "+f"((d)[3])      \
                 : "r"((a)[0]), "r"((a)[1]), "r"((a)[2]), "r"((a)[3]),         \
                   "r"(b0), "r"(b1))

// ---------------- global spin barrier (BB blocks resident) -----------------
__device__ __forceinline__ void gsync() {
    __syncthreads();
    if (threadIdx.x == 0) {
        __threadfence();
        unsigned e = atomicAdd(&g_epoch, 0u);
        if (atomicAdd(&g_barcnt, 1u) == BB - 1u) {
            g_barcnt = 0u;
            __threadfence();
            atomicAdd(&g_epoch, 1u);
        } else {
            while (((volatile unsigned*)&g_epoch)[0] == e) { __nanosleep(64); }
        }
        __threadfence();
    }
    __syncthreads();
}

__device__ __forceinline__ int edge_at(const void* p, int idx, int is64) {
    return is64 ? ((const int*)p)[2 * idx] : ((const int*)p)[idx];
}

// ---------------- fused CSR build (1024 threads x 256 blocks, 2/SM) --------
__global__ __launch_bounds__(BT, 2) void k_build(const void* ei) {
    int t = threadIdx.x, b = blockIdx.x;
    int gid = b * BT + t;
    const int GSTR = BB * BT;

    if (gid == 0) {
        const long long* q = (const long long*)ei;
        int ok = 1;
        for (int j = 0; j < 256; j++) {
            long long v = q[j];
            if (v < 0 || v >= NN) { ok = 0; break; }
        }
        g_is64 = ok;
    }
    for (int i = gid; i < NN; i += GSTR) g_cnt[i] = 0;
    gsync();
    int is64 = g_is64;

    for (int e = gid; e < EE; e += GSTR) {
        int d = edge_at(ei, EE + e, is64);
        atomicAdd(&g_cnt[d], 1);
    }
    gsync();

    __shared__ int s[BT];
    __shared__ int sp[BB];
    int i = gid;
    int x = (i < NN) ? g_cnt[i] : 0;
    if (i < NN) g_dinv[i] = rsqrtf((float)(x + 1));
    s[t] = x;
    __syncthreads();
    for (int off = 1; off < BT; off <<= 1) {
        int v = (t >= off) ? s[t - off] : 0;
        __syncthreads();
        s[t] += v;
        __syncthreads();
    }
    int incl = s[t];
    if (t == BT - 1) g_part[b] = incl;
    gsync();

    if (t < BB) sp[t] = g_part[t];
    __syncthreads();
    for (int off = 1; off < BB; off <<= 1) {
        int v = 0;
        if (t < BB && t >= off) v = sp[t - off];
        __syncthreads();
        if (t < BB) sp[t] += v;
        __syncthreads();
    }
    int pre = (b > 0) ? sp[b - 1] : 0;
    if (i < NN) {
        int rs = pre + incl - x;
        g_rowstart[i] = rs;
        g_next[i] = rs;
    }
    if (gid == 0) g_rowstart[NN] = EE;
    gsync();

    for (int e = gid; e < EE; e += GSTR) {
        int sdx = edge_at(ei, e, is64);
        int dd  = edge_at(ei, EE + e, is64);
        int pos = atomicAdd(&g_next[dd], 1);
        g_edge[pos] = make_int2(sdx, __float_as_int(g_dinv[sdx]));
    }
}

// ---------------- W split to bf16 hi/lo (once per call) ----------------
__global__ void k_wconv(const float* __restrict__ w0, const float* __restrict__ w1,
                        const float* __restrict__ w2) {
    const float* W = (blockIdx.x == 0) ? w0 : ((blockIdx.x == 1) ? w1 : w2);
    __nv_bfloat16* d1 = g_wb[blockIdx.x][0];
    __nv_bfloat16* d2 = g_wb[blockIdx.x][1];
    for (int idx = threadIdx.x; idx < 16384; idx += 256) {
        float v = W[idx];
        __nv_bfloat16 h1 = __float2bfloat16(v);
        float r = v - __bfloat162float(h1);
        d1[idx] = h1;
        d2[idx] = __float2bfloat16(r);
    }
}

// ------ persistent ldmatrix+mma.sync GEMM: C = f(A) @ W, split-bf16 --------
// grid=296 (2 CTAs/SM), 256 threads (8 warps: 4m x 2n, warp tile 16x64).
// 64-row A tiles. XOR-swizzled smem (granule ^ row&7), no padding.
// smem bytes: B1[32K] B2[32K] A1[16K] A2[16K] = 96 KB.
#define B1OFF 0
#define B2OFF 32768
#define A1OFF 65536
#define A2OFF 81920
#define SMEMSZ 98304

__global__ __launch_bounds__(256, 2) void k_gemm_p(
    const float* __restrict__ A, int layer, float* __restrict__ C,
    int tile0, int ntiles, int use_bn, int act)
{
    extern __shared__ unsigned char smb[];
    uint32_t sb = smem_u32(smb);

    int t = threadIdx.x, lane = t & 31, wid = t >> 5;
    int mo = (wid >> 1) * 16;      // warp row offset (4 m-warps x 16)
    int no = (wid & 1) * 64;       // warp col offset (2 n-warps x 64)
    int tend = tile0 + ntiles;

    // stage B hi/lo once, swizzled (granule = 8 bf16 = 16 B)
    {
        const uint4* s1 = (const uint4*)g_wb[layer][0];
        const uint4* s2 = (const uint4*)g_wb[layer][1];
        for (int i = t; i < 2048; i += 256) {
            int row = i >> 4, g = i & 15;
            uint32_t off = (uint32_t)row * 256u + (uint32_t)((g ^ (row & 7)) << 4);
            *(uint4*)(smb + B1OFF + off) = s1[i];
            *(uint4*)(smb + B2OFF + off) = s2[i];
        }
    }

    // ldmatrix lane geometry
    int lr = (lane & 7) + (lane & 8);     // 0..15
    int lc = (lane >> 4) & 1;             // 0/1 (second 8x8 column block)

    for (int tile = tile0 + blockIdx.x; tile < tend; tile += gridDim.x) {
        int r0 = tile * 64;
        // stage A split-bf16 with fused BN/act, swizzled
#pragma unroll
        for (int j = 0; j < 8; j++) {
            int i = t + j * 256;
            int row = i >> 5, col = (i & 31) * 4;
            int gr = r0 + row;
            float4 v = (gr < NN) ? *(const float4*)(A + (size_t)gr * DD + col)
                                 : make_float4(0.f, 0.f, 0.f, 0.f);
            if (use_bn) {
                v.x = v.x * g_scale[col + 0] + g_shift[col + 0];
                v.y = v.y * g_scale[col + 1] + g_shift[col + 1];
                v.z = v.z * g_scale[col + 2] + g_shift[col + 2];
                v.w = v.w * g_scale[col + 3] + g_shift[col + 3];
                if (act) {
                    v.x = v.x >= 0.f ? v.x : SLOPE * v.x;
                    v.y = v.y >= 0.f ? v.y : SLOPE * v.y;
                    v.z = v.z >= 0.f ? v.z : SLOPE * v.z;
                    v.w = v.w >= 0.f ? v.w : SLOPE * v.w;
                }
            }
            __nv_bfloat162 h1a = make_bfloat162(__float2bfloat16(v.x), __float2bfloat16(v.y));
            __nv_bfloat162 h1b = make_bfloat162(__float2bfloat16(v.z), __float2bfloat16(v.w));
            float rx = v.x - __bfloat162float(h1a.x);
            float ry = v.y - __bfloat162float(h1a.y);
            float rz = v.z - __bfloat162float(h1b.x);
            float rw = v.w - __bfloat162float(h1b.y);
            __nv_bfloat162 h2a = make_bfloat162(__float2bfloat16(rx), __float2bfloat16(ry));
            __nv_bfloat162 h2b = make_bfloat162(__float2bfloat16(rz), __float2bfloat16(rw));
            uint32_t off = (uint32_t)row * 256u
                         + (uint32_t)((((col >> 3) ^ (row & 7)) << 4))
                         + (uint32_t)((col & 4) << 1);   // 8-byte half of granule
            uint2 u1, u2;
            u1.x = *(uint32_t*)&h1a; u1.y = *(uint32_t*)&h1b;
            u2.x = *(uint32_t*)&h2a; u2.y = *(uint32_t*)&h2b;
            *(uint2*)(smb + A1OFF + off) = u1;
            *(uint2*)(smb + A2OFF + off) = u2;
        }
        __syncthreads();

        float acc[8][4];
#pragma unroll
        for (int j = 0; j < 8; j++)
#pragma unroll
            for (int q = 0; q < 4; q++) acc[j][q] = 0.f;

#pragma unroll
        for (int ks = 0; ks < 8; ks++) {
            // A fragments (hi/lo): m16k16 at rows mo.., k-granules ks*2 + lc
            uint32_t a1r[4], a2r[4];
            {
                uint32_t arow = (uint32_t)(mo + lr);
                uint32_t ag = (uint32_t)(ks * 2 + lc);
                uint32_t aoff = arow * 256u + ((ag ^ (arow & 7u)) << 4);
                LDSM4(a1r, sb + A1OFF + aoff);
                LDSM4(a2r, sb + A2OFF + aoff);
            }
            // B fragments: 4 x4.trans per buffer cover n = no..no+63
            uint32_t b1r[16], b2r[16];
            {
                uint32_t brow = (uint32_t)(ks * 16 + lr);
                uint32_t bx = brow & 7u;
#pragma unroll
                for (int nf = 0; nf < 4; nf++) {
                    uint32_t bg = (uint32_t)((no >> 3) + nf * 2 + lc);
                    uint32_t boff = brow * 256u + ((bg ^ bx) << 4);
                    LDSM4T(&b1r[nf * 4], sb + B1OFF + boff);
                    LDSM4T(&b2r[nf * 4], sb + B2OFF + boff);
                }
            }
#pragma unroll
            for (int j = 0; j < 8; j++) {
                int ri = (j >> 1) * 4 + (j & 1) * 2;
                uint32_t h0 = b1r[ri], h1v = b1r[ri + 1];
                uint32_t l0 = b2r[ri], l1v = b2r[ri + 1];
                MMA16816(acc[j], a1r, h0, h1v);
                MMA16816(acc[j], a2r, h0, h1v);
                MMA16816(acc[j], a1r, l0, l1v);
            }
        }

        // epilogue: m16n8 accumulator lane mapping, direct float2 stores
        int rbase = r0 + mo;                  // NN % 16 == 0: strip all-in/out
        if (rbase + 16 <= NN) {
            int rr = rbase + (lane >> 2);
            int cc = no + (lane & 3) * 2;
#pragma unroll
            for (int j = 0; j < 8; j++) {
                *(float2*)(C + (size_t)rr * DD + cc + j * 8) =
                    make_float2(acc[j][0], acc[j][1]);
                *(float2*)(C + (size_t)(rr + 8) * DD + cc + j * 8) =
                    make_float2(acc[j][2], acc[j][3]);
            }
        }
        __syncthreads();   // compute done before next iteration restages A
    }
}

// ---- aggregation: warp/node CSR gather + store-based BN-stats partials ----
__global__ __launch_bounds__(256, 7) void k_agg(
    const float* __restrict__ xw, float* __restrict__ outp,
    float* __restrict__ psum, float* __restrict__ psq)
{
    __shared__ float s1[8][128], s2[8][128];
    int t = threadIdx.x;
    int wid = t >> 5, lane = t & 31;
    int w = blockIdx.x * 8 + wid;
    float di = g_dinv[w];

    float4 acc = __ldg(reinterpret_cast<const float4*>(xw + (size_t)w * DD) + lane);
    float cself = di * di;
    acc.x *= cself; acc.y *= cself; acc.z *= cself; acc.w *= cself;

    int beg = g_rowstart[w], end = g_rowstart[w + 1];
    int i = beg;
    for (; i + 3 < end; i += 4) {
        int2 e0 = __ldg(&g_edge[i + 0]);
        int2 e1 = __ldg(&g_edge[i + 1]);
        int2 e2 = __ldg(&g_edge[i + 2]);
        int2 e3 = __ldg(&g_edge[i + 3]);
        float4 v0 = __ldg(reinterpret_cast<const float4*>(xw + (size_t)e0.x * DD) + lane);
        float4 v1 = __ldg(reinterpret_cast<const float4*>(xw + (size_t)e1.x * DD) + lane);
        float4 v2 = __ldg(reinterpret_cast<const float4*>(xw + (size_t)e2.x * DD) + lane);
        float4 v3 = __ldg(reinterpret_cast<const float4*>(xw + (size_t)e3.x * DD) + lane);
        float c0 = di * __int_as_float(e0.y);
        float c1 = di * __int_as_float(e1.y);
        float c2 = di * __int_as_float(e2.y);
        float c3 = di * __int_as_float(e3.y);
        acc.x = fmaf(c0, v0.x, acc.x); acc.y = fmaf(c0, v0.y, acc.y);
        acc.z = fmaf(c0, v0.z, acc.z); acc.w = fmaf(c0, v0.w, acc.w);
        acc.x = fmaf(c1, v1.x, acc.x); acc.y = fmaf(c1, v1.y, acc.y);
        acc.z = fmaf(c1, v1.z, acc.z); acc.w = fmaf(c1, v1.w, acc.w);
        acc.x = fmaf(c2, v2.x, acc.x); acc.y = fmaf(c2, v2.y, acc.y);
        acc.z = fmaf(c2, v2.z, acc.z); acc.w = fmaf(c2, v2.w, acc.w);
        acc.x = fmaf(c3, v3.x, acc.x); acc.y = fmaf(c3, v3.y, acc.y);
        acc.z = fmaf(c3, v3.z, acc.z); acc.w = fmaf(c3, v3.w, acc.w);
    }
    if (i < end) {
        int last = end - 1;
        int2 e0 = __ldg(&g_edge[i]);
        int2 e1 = __ldg(&g_edge[min(i + 1, last)]);
        int2 e2 = __ldg(&g_edge[min(i + 2, last)]);
        float4 v0 = __ldg(reinterpret_cast<const float4*>(xw + (size_t)e0.x * DD) + lane);
        float4 v1 = __ldg(reinterpret_cast<const float4*>(xw + (size_t)e1.x * DD) + lane);
        float4 v2 = __ldg(reinterpret_cast<const float4*>(xw + (size_t)e2.x * DD) + lane);
        float c0 = di * __int_as_float(e0.y);
        float c1 = (i + 1 < end) ? di * __int_as_float(e1.y) : 0.f;
        float c2 = (i + 2 < end) ? di * __int_as_float(e2.y) : 0.f;
        acc.x = fmaf(c0, v0.x, acc.x); acc.y = fmaf(c0, v0.y, acc.y);
        acc.z = fmaf(c0, v0.z, acc.z); acc.w = fmaf(c0, v0.w, acc.w);
        acc.x = fmaf(c1, v1.x, acc.x); acc.y = fmaf(c1, v1.y, acc.y);
        acc.z = fmaf(c1, v1.z, acc.z); acc.w = fmaf(c1, v1.w, acc.w);
        acc.x = fmaf(c2, v2.x, acc.x); acc.y = fmaf(c2, v2.y, acc.y);
        acc.z = fmaf(c2, v2.z, acc.z); acc.w = fmaf(c2, v2.w, acc.w);
    }
    reinterpret_cast<float4*>(outp + (size_t)w * DD)[lane] = acc;

    reinterpret_cast<float4*>(&s1[wid][0])[lane] = acc;
    reinterpret_cast<float4*>(&s2[wid][0])[lane] =
        make_float4(acc.x * acc.x, acc.y * acc.y, acc.z * acc.z, acc.w * acc.w);
    __syncthreads();
    if (t < 128) {
        float a = 0.f, b = 0.f;
#pragma unroll
        for (int ww = 0; ww < 8; ww++) { a += s1[ww][t]; b += s2[ww][t]; }
        psum[(size_t)blockIdx.x * DD + t] = a;
        psq [(size_t)blockIdx.x * DD + t] = b;
    }
}

// ---------------- BN stats finalize: block per feature ----------------
__global__ __launch_bounds__(256) void k_stats2(
    const float* __restrict__ gw, const float* __restrict__ be)
{
    __shared__ double r1[256], r2[256];
    int d = blockIdx.x;
    double s = 0.0, q = 0.0;
    for (int b = threadIdx.x; b < NBLK; b += 256) {
        s += (double)g_psum[(size_t)b * DD + d];
        q += (double)g_psq [(size_t)b * DD + d];
    }
    r1[threadIdx.x] = s; r2[threadIdx.x] = q;
    __syncthreads();
    for (int off = 128; off > 0; off >>= 1) {
        if (threadIdx.x < off) {
            r1[threadIdx.x] += r1[threadIdx.x + off];
            r2[threadIdx.x] += r2[threadIdx.x + off];
        }
        __syncthreads();
    }
    if (threadIdx.x == 0) {
        double mu = r1[0] / (double)NN;
        double var = r2[0] / (double)NN - mu * mu;
        float inv = (float)(1.0 / sqrt(var + 1e-5));
        float scl = gw[d] * inv;
        g_scale[d] = scl;
        g_shift[d] = be[d] - (float)mu * scl;
    }
}

// ---------------- final BN apply ----------------
__global__ void k_apply(float* __restrict__ h) {
    int idx = blockIdx.x * blockDim.x + threadIdx.x;
    if (idx < NN * DD / 4) {
        float4 v = reinterpret_cast<float4*>(h)[idx];
        int d = (idx & 31) * 4;
        v.x = v.x * g_scale[d + 0] + g_shift[d + 0];
        v.y = v.y * g_scale[d + 1] + g_shift[d + 1];
        v.z = v.z * g_scale[d + 2] + g_shift[d + 2];
        v.w = v.w * g_scale[d + 3] + g_shift[d + 3];
        reinterpret_cast<float4*>(h)[idx] = v;
    }
}

// ---------------- host launcher ----------------
extern "C" void kernel_launch(void* const* d_in, const int* in_sizes, int n_in,
                              void* d_out, int out_size) {
    const float* x   = (const float*)d_in[0];
    const void*  ei  = d_in[1];
    const float* w0  = (const float*)d_in[2];
    const float* g0  = (const float*)d_in[4];
    const float* be0 = (const float*)d_in[5];
    const float* w1  = (const float*)d_in[6];
    const float* g1  = (const float*)d_in[8];
    const float* be1 = (const float*)d_in[9];
    const float* w2  = (const float*)d_in[10];
    const float* g2  = (const float*)d_in[12];
    const float* be2 = (const float*)d_in[13];
    float* out = (float*)d_out;

    float *xw, *h, *ps, *pq;
    cudaGetSymbolAddress((void**)&xw, g_xw);
    cudaGetSymbolAddress((void**)&h,  g_h);
    cudaGetSymbolAddress((void**)&ps, g_psum);
    cudaGetSymbolAddress((void**)&pq, g_psq);

    static int smem_set = 0;
    if (!smem_set) {
        cudaFuncSetAttribute(k_gemm_p, cudaFuncAttributeMaxDynamicSharedMemorySize, SMEMSZ);
        smem_set = 1;
    }

    const int TB = 256;
    const int GTILES = (NN + 63) / 64;     // 938
    const int GH = GTILES / 2;             // 469
    int gbP = (NN * DD / 4 + TB - 1) / TB;

    // layer 0 (launch #4 = GEMM second half -> ncu capture slot)
    k_build<<<BB, BT>>>(ei);                                               // 1
    k_wconv<<<3, TB>>>(w0, w1, w2);                                        // 2
    k_gemm_p<<<GEMM_GRID, TB, SMEMSZ>>>(x, 0, xw, 0, GH, 0, 0);            // 3
    k_gemm_p<<<GEMM_GRID, TB, SMEMSZ>>>(x, 0, xw, GH, GTILES - GH, 0, 0);  // 4 <- profiled
    k_agg<<<NBLK, TB>>>(xw, h, ps, pq);                                    // 5
    k_stats2<<<DD, TB>>>(g0, be0);                                         // 6

    // layer 1 (BN0 + LeakyReLU fused into A staging)
    k_gemm_p<<<GEMM_GRID, TB, SMEMSZ>>>(h, 1, xw, 0, GTILES, 1, 1);
    k_agg<<<NBLK, TB>>>(xw, h, ps, pq);
    k_stats2<<<DD, TB>>>(g1, be1);

    // layer 2 (BN1 + LeakyReLU fused), final BN standalone
    k_gemm_p<<<GEMM_GRID, TB, SMEMSZ>>>(h, 2, xw, 0, GTILES, 1, 1);
    k_agg<<<NBLK, TB>>>(xw, out, ps, pq);
    k_stats2<<<DD, TB>>>(g2, be2);
    k_apply<<<gbP, TB>>>(out);
}

// round 14
// speedup vs baseline: 1.2833x; 1.0905x over previous
#include <cuda_runtime.h>
#include <cuda_fp16.h>
#include <cstdint>

#define NN 60000
#define EE 600000
#define DD 128
#define SLOPE 0.01f
#define BB 256            // build blocks (co-resident @ 2/SM)
#define BT 1024           // build threads
#define NBLK 7500         // agg stats partial blocks (60000/8)

typedef unsigned long long ull;

// ---------------- device scratch (static, no allocation) ----------------
__device__ int   g_is64;
__device__ int   g_cnt[NN];
__device__ int   g_part[BB];
__device__ int   g_rowstart[NN + 1];
__device__ int   g_next[NN];
__device__ int2  g_edge[EE];
__device__ float g_dinv[NN];
__device__ float g_xw[(size_t)NN * DD];
__device__ float g_h[(size_t)NN * DD];
__device__ float g_psum[(size_t)NBLK * DD];
__device__ float g_psq[(size_t)NBLK * DD];
__device__ float g_scale[DD];
__device__ float g_shift[DD];
__device__ unsigned g_barcnt;
__device__ unsigned g_epoch;
// W as fp16, row-major [k][n]: [layer][128*128]
__device__ __align__(16) __half g_wh[3][16384];

// ---------------- mma.sync / ldmatrix primitives ----------------
__device__ __forceinline__ uint32_t smem_u32(const void* p) {
    return (uint32_t)__cvta_generic_to_shared(p);
}
#define LDSM4(r, addr)                                                         \
    asm volatile("ldmatrix.sync.aligned.m8n8.x4.shared.b16 {%0,%1,%2,%3}, [%4];" \
                 : "=r"((r)[0]), "=r"((r)[1]), "=r"((r)[2]), "=r"((r)[3])      \
                 : "r"(addr))
#define LDSM4T(r, addr)                                                        \
    asm volatile("ldmatrix.sync.aligned.m8n8.x4.trans.shared.b16 {%0,%1,%2,%3}, [%4];" \
                 : "=r"((r)[0]), "=r"((r)[1]), "=r"((r)[2]), "=r"((r)[3])      \
                 : "r"(addr))
#define MMA16816H(d, a, b0, b1)                                                \
    asm volatile("mma.sync.aligned.m16n8k16.row.col.f32.f16.f16.f32 "          \
                 "{%0,%1,%2,%3},{%4,%5,%6,%7},{%8,%9},{%0,%1,%2,%3};"          \
                 : "+f"((d)[0]), "+f"((d)[1]), "+f"((d)[2]), "+f"((d)[3])      \
                 : "r"((a)[0]), "r"((a)[1]), "r"((a)[2]), "r"((a)[3]),         \
                   "r"(b0), "r"(b1))

// ---------------- global spin barrier (BB blocks resident) -----------------
__device__ __forceinline__ void gsync() {
    __syncthreads();
    if (threadIdx.x == 0) {
        __threadfence();
        unsigned e = atomicAdd(&g_epoch, 0u);
        if (atomicAdd(&g_barcnt, 1u) == BB - 1u) {
            g_barcnt = 0u;
            __threadfence();
            atomicAdd(&g_epoch, 1u);
        } else {
            while (((volatile unsigned*)&g_epoch)[0] == e) { __nanosleep(64); }
        }
        __threadfence();
    }
    __syncthreads();
}

__device__ __forceinline__ int edge_at(const void* p, int idx, int is64) {
    return is64 ? ((const int*)p)[2 * idx] : ((const int*)p)[idx];
}

// ---------------- fused CSR build (1024 threads x 256 blocks, 2/SM) --------
__global__ __launch_bounds__(BT, 2) void k_build(const void* ei) {
    int t = threadIdx.x, b = blockIdx.x;
    int gid = b * BT + t;
    const int GSTR = BB * BT;

    if (gid == 0) {
        const long long* q = (const long long*)ei;
        int ok = 1;
        for (int j = 0; j < 256; j++) {
            long long v = q[j];
            if (v < 0 || v >= NN) { ok = 0; break; }
        }
        g_is64 = ok;
    }
    for (int i = gid; i < NN; i += GSTR) g_cnt[i] = 0;
    gsync();
    int is64 = g_is64;

    for (int e = gid; e < EE; e += GSTR) {
        int d = edge_at(ei, EE + e, is64);
        atomicAdd(&g_cnt[d], 1);
    }
    gsync();

    __shared__ int s[BT];
    __shared__ int sp[BB];
    int i = gid;
    int x = (i < NN) ? g_cnt[i] : 0;
    if (i < NN) g_dinv[i] = rsqrtf((float)(x + 1));
    s[t] = x;
    __syncthreads();
    for (int off = 1; off < BT; off <<= 1) {
        int v = (t >= off) ? s[t - off] : 0;
        __syncthreads();
        s[t] += v;
        __syncthreads();
    }
    int incl = s[t];
    if (t == BT - 1) g_part[b] = incl;
    gsync();

    if (t < BB) sp[t] = g_part[t];
    __syncthreads();
    for (int off = 1; off < BB; off <<= 1) {
        int v = 0;
        if (t < BB && t >= off) v = sp[t - off];
        __syncthreads();
        if (t < BB) sp[t] += v;
        __syncthreads();
    }
    int pre = (b > 0) ? sp[b - 1] : 0;
    if (i < NN) {
        int rs = pre + incl - x;
        g_rowstart[i] = rs;
        g_next[i] = rs;
    }
    if (gid == 0) g_rowstart[NN] = EE;
    gsync();

    for (int e = gid; e < EE; e += GSTR) {
        int sdx = edge_at(ei, e, is64);
        int dd  = edge_at(ei, EE + e, is64);
        int pos = atomicAdd(&g_next[dd], 1);
        g_edge[pos] = make_int2(sdx, __float_as_int(g_dinv[sdx]));
    }
}

// ---------------- W convert to fp16 (once per call) ----------------
__global__ void k_wconv(const float* __restrict__ w0, const float* __restrict__ w1,
                        const float* __restrict__ w2) {
    const float* W = (blockIdx.x == 0) ? w0 : ((blockIdx.x == 1) ? w1 : w2);
    __half* d1 = g_wh[blockIdx.x];
    for (int idx = threadIdx.x; idx < 16384; idx += 256) {
        d1[idx] = __float2half(W[idx]);
    }
}

// ------ persistent ldmatrix+mma.sync fp16 GEMM: C = f(A) @ W ---------------
// 256 threads (8 warps: 4m x 2n, warp tile 16x64), 64-row A tiles.
// Single fp16 product, f32 accumulate. XOR-swizzled smem, 48 KB static.
#define BOFF 0
#define AOFF 32768

__global__ __launch_bounds__(256, 3) void k_gemm_p(
    const float* __restrict__ A, int layer, float* __restrict__ C,
    int tile0, int ntiles, int use_bn, int act)
{
    __shared__ unsigned char smb[49152];
    uint32_t sb = smem_u32(smb);

    int t = threadIdx.x, lane = t & 31, wid = t >> 5;
    int mo = (wid >> 1) * 16;      // warp row offset (4 m-warps x 16)
    int no = (wid & 1) * 64;       // warp col offset (2 n-warps x 64)
    int tend = tile0 + ntiles;

    // stage W fp16 once, swizzled (granule = 8 fp16 = 16 B)
    {
        const uint4* s1 = (const uint4*)g_wh[layer];
        for (int i = t; i < 2048; i += 256) {
            int row = i >> 4, g = i & 15;
            uint32_t off = (uint32_t)row * 256u + (uint32_t)((g ^ (row & 7)) << 4);
            *(uint4*)(smb + BOFF + off) = s1[i];
        }
    }

    // ldmatrix lane geometry
    int lr = (lane & 7) + (lane & 8);     // 0..15
    int lc = (lane >> 4) & 1;             // 0/1 (second 8x8 block)

    for (int tile = tile0 + blockIdx.x; tile < tend; tile += gridDim.x) {
        int r0 = tile * 64;
        // stage A fp16 with fused BN/act, swizzled
#pragma unroll
        for (int j = 0; j < 8; j++) {
            int i = t + j * 256;
            int row = i >> 5, col = (i & 31) * 4;
            int gr = r0 + row;
            float4 v = (gr < NN) ? *(const float4*)(A + (size_t)gr * DD + col)
                                 : make_float4(0.f, 0.f, 0.f, 0.f);
            if (use_bn) {
                v.x = v.x * g_scale[col + 0] + g_shift[col + 0];
                v.y = v.y * g_scale[col + 1] + g_shift[col + 1];
                v.z = v.z * g_scale[col + 2] + g_shift[col + 2];
                v.w = v.w * g_scale[col + 3] + g_shift[col + 3];
                if (act) {
                    v.x = v.x >= 0.f ? v.x : SLOPE * v.x;
                    v.y = v.y >= 0.f ? v.y : SLOPE * v.y;
                    v.z = v.z >= 0.f ? v.z : SLOPE * v.z;
                    v.w = v.w >= 0.f ? v.w : SLOPE * v.w;
                }
            }
            __half2 ha = __floats2half2_rn(v.x, v.y);
            __half2 hb = __floats2half2_rn(v.z, v.w);
            uint32_t off = (uint32_t)row * 256u
                         + (uint32_t)((((col >> 3) ^ (row & 7)) << 4))
                         + (uint32_t)((col & 4) << 1);
            uint2 u;
            u.x = *(uint32_t*)&ha; u.y = *(uint32_t*)&hb;
            *(uint2*)(smb + AOFF + off) = u;
        }
        __syncthreads();

        float acc[8][4];
#pragma unroll
        for (int j = 0; j < 8; j++)
#pragma unroll
            for (int q = 0; q < 4; q++) acc[j][q] = 0.f;

#pragma unroll
        for (int ks = 0; ks < 8; ks++) {
            uint32_t ar[4];
            {
                uint32_t arow = (uint32_t)(mo + lr);
                uint32_t ag = (uint32_t)(ks * 2 + lc);
                uint32_t aoff = arow * 256u + ((ag ^ (arow & 7u)) << 4);
                LDSM4(ar, sb + AOFF + aoff);
            }
            uint32_t br[16];
            {
                uint32_t brow = (uint32_t)(ks * 16 + lr);
                uint32_t bx = brow & 7u;
#pragma unroll
                for (int nf = 0; nf < 4; nf++) {
                    uint32_t bg = (uint32_t)((no >> 3) + nf * 2 + lc);
                    uint32_t boff = brow * 256u + ((bg ^ bx) << 4);
                    LDSM4T(&br[nf * 4], sb + BOFF + boff);
                }
            }
#pragma unroll
            for (int j = 0; j < 8; j++) {
                int ri = (j >> 1) * 4 + (j & 1) * 2;
                MMA16816H(acc[j], ar, br[ri], br[ri + 1]);
            }
        }

        // epilogue: m16n8 accumulator lane mapping, direct float2 stores
        int rbase = r0 + mo;                  // NN % 16 == 0: strip all-in/out
        if (rbase + 16 <= NN) {
            int rr = rbase + (lane >> 2);
            int cc = no + (lane & 3) * 2;
#pragma unroll
            for (int j = 0; j < 8; j++) {
                *(float2*)(C + (size_t)rr * DD + cc + j * 8) =
                    make_float2(acc[j][0], acc[j][1]);
                *(float2*)(C + (size_t)(rr + 8) * DD + cc + j * 8) =
                    make_float2(acc[j][2], acc[j][3]);
            }
        }
        __syncthreads();   // compute done before next iteration restages A
    }
}

// ---- aggregation: warp/node CSR gather + store-based BN-stats partials ----
__global__ __launch_bounds__(256, 7) void k_agg(
    const float* __restrict__ xw, float* __restrict__ outp,
    float* __restrict__ psum, float* __restrict__ psq)
{
    __shared__ float s1[8][128], s2[8][128];
    int t = threadIdx.x;
    int wid = t >> 5, lane = t & 31;
    int w = blockIdx.x * 8 + wid;
    float di = g_dinv[w];

    float4 acc = __ldg(reinterpret_cast<const float4*>(xw + (size_t)w * DD) + lane);
    float cself = di * di;
    acc.x *= cself; acc.y *= cself; acc.z *= cself; acc.w *= cself;

    int beg = g_rowstart[w], end = g_rowstart[w + 1];
    int i = beg;
    for (; i + 3 < end; i += 4) {
        int2 e0 = __ldg(&g_edge[i + 0]);
        int2 e1 = __ldg(&g_edge[i + 1]);
        int2 e2 = __ldg(&g_edge[i + 2]);
        int2 e3 = __ldg(&g_edge[i + 3]);
        float4 v0 = __ldg(reinterpret_cast<const float4*>(xw + (size_t)e0.x * DD) + lane);
        float4 v1 = __ldg(reinterpret_cast<const float4*>(xw + (size_t)e1.x * DD) + lane);
        float4 v2 = __ldg(reinterpret_cast<const float4*>(xw + (size_t)e2.x * DD) + lane);
        float4 v3 = __ldg(reinterpret_cast<const float4*>(xw + (size_t)e3.x * DD) + lane);
        float c0 = di * __int_as_float(e0.y);
        float c1 = di * __int_as_float(e1.y);
        float c2 = di * __int_as_float(e2.y);
        float c3 = di * __int_as_float(e3.y);
        acc.x = fmaf(c0, v0.x, acc.x); acc.y = fmaf(c0, v0.y, acc.y);
        acc.z = fmaf(c0, v0.z, acc.z); acc.w = fmaf(c0, v0.w, acc.w);
        acc.x = fmaf(c1, v1.x, acc.x); acc.y = fmaf(c1, v1.y, acc.y);
        acc.z = fmaf(c1, v1.z, acc.z); acc.w = fmaf(c1, v1.w, acc.w);
        acc.x = fmaf(c2, v2.x, acc.x); acc.y = fmaf(c2, v2.y, acc.y);
        acc.z = fmaf(c2, v2.z, acc.z); acc.w = fmaf(c2, v2.w, acc.w);
        acc.x = fmaf(c3, v3.x, acc.x); acc.y = fmaf(c3, v3.y, acc.y);
        acc.z = fmaf(c3, v3.z, acc.z); acc.w = fmaf(c3, v3.w, acc.w);
    }
    if (i < end) {
        int last = end - 1;
        int2 e0 = __ldg(&g_edge[i]);
        int2 e1 = __ldg(&g_edge[min(i + 1, last)]);
        int2 e2 = __ldg(&g_edge[min(i + 2, last)]);
        float4 v0 = __ldg(reinterpret_cast<const float4*>(xw + (size_t)e0.x * DD) + lane);
        float4 v1 = __ldg(reinterpret_cast<const float4*>(xw + (size_t)e1.x * DD) + lane);
        float4 v2 = __ldg(reinterpret_cast<const float4*>(xw + (size_t)e2.x * DD) + lane);
        float c0 = di * __int_as_float(e0.y);
        float c1 = (i + 1 < end) ? di * __int_as_float(e1.y) : 0.f;
        float c2 = (i + 2 < end) ? di * __int_as_float(e2.y) : 0.f;
        acc.x = fmaf(c0, v0.x, acc.x); acc.y = fmaf(c0, v0.y, acc.y);
        acc.z = fmaf(c0, v0.z, acc.z); acc.w = fmaf(c0, v0.w, acc.w);
        acc.x = fmaf(c1, v1.x, acc.x); acc.y = fmaf(c1, v1.y, acc.y);
        acc.z = fmaf(c1, v1.z, acc.z); acc.w = fmaf(c1, v1.w, acc.w);
        acc.x = fmaf(c2, v2.x, acc.x); acc.y = fmaf(c2, v2.y, acc.y);
        acc.z = fmaf(c2, v2.z, acc.z); acc.w = fmaf(c2, v2.w, acc.w);
    }
    reinterpret_cast<float4*>(outp + (size_t)w * DD)[lane] = acc;

    reinterpret_cast<float4*>(&s1[wid][0])[lane] = acc;
    reinterpret_cast<float4*>(&s2[wid][0])[lane] =
        make_float4(acc.x * acc.x, acc.y * acc.y, acc.z * acc.z, acc.w * acc.w);
    __syncthreads();
    if (t < 128) {
        float a = 0.f, b = 0.f;
#pragma unroll
        for (int ww = 0; ww < 8; ww++) { a += s1[ww][t]; b += s2[ww][t]; }
        psum[(size_t)blockIdx.x * DD + t] = a;
        psq [(size_t)blockIdx.x * DD + t] = b;
    }
}

// ---------------- BN stats finalize: block per feature ----------------
__global__ __launch_bounds__(256) void k_stats2(
    const float* __restrict__ gw, const float* __restrict__ be)
{
    __shared__ double r1[256], r2[256];
    int d = blockIdx.x;
    double s = 0.0, q = 0.0;
    for (int b = threadIdx.x; b < NBLK; b += 256) {
        s += (double)g_psum[(size_t)b * DD + d];
        q += (double)g_psq [(size_t)b * DD + d];
    }
    r1[threadIdx.x] = s; r2[threadIdx.x] = q;
    __syncthreads();
    for (int off = 128; off > 0; off >>= 1) {
        if (threadIdx.x < off) {
            r1[threadIdx.x] += r1[threadIdx.x + off];
            r2[threadIdx.x] += r2[threadIdx.x + off];
        }
        __syncthreads();
    }
    if (threadIdx.x == 0) {
        double mu = r1[0] / (double)NN;
        double var = r2[0] / (double)NN - mu * mu;
        float inv = (float)(1.0 / sqrt(var + 1e-5));
        float scl = gw[d] * inv;
        g_scale[d] = scl;
        g_shift[d] = be[d] - (float)mu * scl;
    }
}

// ---------------- final BN apply ----------------
__global__ void k_apply(float* __restrict__ h) {
    int idx = blockIdx.x * blockDim.x + threadIdx.x;
    if (idx < NN * DD / 4) {
        float4 v = reinterpret_cast<float4*>(h)[idx];
        int d = (idx & 31) * 4;
        v.x = v.x * g_scale[d + 0] + g_shift[d + 0];
        v.y = v.y * g_scale[d + 1] + g_shift[d + 1];
        v.z = v.z * g_scale[d + 2] + g_shift[d + 2];
        v.w = v.w * g_scale[d + 3] + g_shift[d + 3];
        reinterpret_cast<float4*>(h)[idx] = v;
    }
}

// ---------------- host launcher ----------------
extern "C" void kernel_launch(void* const* d_in, const int* in_sizes, int n_in,
                              void* d_out, int out_size) {
    const float* x   = (const float*)d_in[0];
    const void*  ei  = d_in[1];
    const float* w0  = (const float*)d_in[2];
    const float* g0  = (const float*)d_in[4];
    const float* be0 = (const float*)d_in[5];
    const float* w1  = (const float*)d_in[6];
    const float* g1  = (const float*)d_in[8];
    const float* be1 = (const float*)d_in[9];
    const float* w2  = (const float*)d_in[10];
    const float* g2  = (const float*)d_in[12];
    const float* be2 = (const float*)d_in[13];
    float* out = (float*)d_out;

    float *xw, *h, *ps, *pq;
    cudaGetSymbolAddress((void**)&xw, g_xw);
    cudaGetSymbolAddress((void**)&h,  g_h);
    cudaGetSymbolAddress((void**)&ps, g_psum);
    cudaGetSymbolAddress((void**)&pq, g_psq);

    const int TB = 256;
    const int GTILES = (NN + 63) / 64;     // 938
    const int GH = GTILES / 2;             // 469
    const int GGRID = 592;                 // 4 CTAs/SM target (3 by bounds)
    int gbP = (NN * DD / 4 + TB - 1) / TB;

    // layer 0 (launch #4 = fp16 GEMM second half -> ncu capture slot)
    k_build<<<BB, BT>>>(ei);                                        // 1
    k_wconv<<<3, TB>>>(w0, w1, w2);                                 // 2
    k_gemm_p<<<GH, TB>>>(x, 0, xw, 0, GH, 0, 0);                    // 3
    k_gemm_p<<<GTILES - GH, TB>>>(x, 0, xw, GH, GTILES - GH, 0, 0); // 4 <- profiled
    k_agg<<<NBLK, TB>>>(xw, h, ps, pq);                             // 5
    k_stats2<<<DD, TB>>>(g0, be0);                                  // 6

    // layer 1 (BN0 + LeakyReLU fused into A staging)
    k_gemm_p<<<GGRID, TB>>>(h, 1, xw, 0, GTILES, 1, 1);
    k_agg<<<NBLK, TB>>>(xw, h, ps, pq);
    k_stats2<<<DD, TB>>>(g1, be1);

    // layer 2 (BN1 + LeakyReLU fused), final BN standalone
    k_gemm_p<<<GGRID, TB>>>(h, 2, xw, 0, GTILES, 1, 1);
    k_agg<<<NBLK, TB>>>(xw, out, ps, pq);
    k_stats2<<<DD, TB>>>(g2, be2);
    k_apply<<<gbP, TB>>>(out);
}

// round 15
// speedup vs baseline: 1.3029x; 1.0153x over previous
#include <cuda_runtime.h>
#include <cuda_fp16.h>
#include <cstdint>

#define NN 60000
#define EE 600000
#define DD 128
#define SLOPE 0.01f
#define BB 256            // build blocks (co-resident @ 2/SM)
#define BT 1024           // build threads
#define NBLK 7500         // agg stats partial blocks (60000/8)
#define GEMM_GRID 296     // persistent GEMM: 2 CTAs/SM

typedef unsigned long long ull;

// ---------------- device scratch (static, no allocation) ----------------
__device__ int   g_is64;
__device__ int   g_cnt[NN];
__device__ int   g_part[BB];
__device__ int   g_rowstart[NN + 1];
__device__ int   g_next[NN];
__device__ int2  g_edge[EE];
__device__ float g_dinv[NN];
__device__ float g_xw[(size_t)NN * DD];
__device__ float g_h[(size_t)NN * DD];
__device__ float g_psum[(size_t)NBLK * DD];
__device__ float g_psq[(size_t)NBLK * DD];
__device__ float g_scale[DD];
__device__ float g_shift[DD];
__device__ unsigned g_barcnt;
__device__ unsigned g_epoch;
// W as fp16, row-major [k][n]: [layer][128*128]
__device__ __align__(16) __half g_wh[3][16384];

// ---------------- mma.sync / ldmatrix primitives ----------------
__device__ __forceinline__ uint32_t smem_u32(const void* p) {
    return (uint32_t)__cvta_generic_to_shared(p);
}
#define LDSM4(r, addr)                                                         \
    asm volatile("ldmatrix.sync.aligned.m8n8.x4.shared.b16 {%0,%1,%2,%3}, [%4];" \
                 : "=r"((r)[0]), "=r"((r)[1]), "=r"((r)[2]), "=r"((r)[3])      \
                 : "r"(addr))
#define LDSM4T(r, addr)                                                        \
    asm volatile("ldmatrix.sync.aligned.m8n8.x4.trans.shared.b16 {%0,%1,%2,%3}, [%4];" \
                 : "=r"((r)[0]), "=r"((r)[1]), "=r"((r)[2]), "=r"((r)[3])      \
                 : "r"(addr))
#define MMA16816H(d, a, b0, b1)                                                \
    asm volatile("mma.sync.aligned.m16n8k16.row.col.f32.f16.f16.f32 "          \
                 "{%0,%1,%2,%3},{%4,%5,%6,%7},{%8,%9},{%0,%1,%2,%3};"          \
                 : "+f"((d)[0]), "+f"((d)[1]), "+f"((d)[2]), "+f"((d)[3])      \
                 : "r"((a)[0]), "r"((a)[1]), "r"((a)[2]), "r"((a)[3]),         \
                   "r"(b0), "r"(b1))

// ---------------- global spin barrier (BB blocks resident) -----------------
__device__ __forceinline__ void gsync() {
    __syncthreads();
    if (threadIdx.x == 0) {
        __threadfence();
        unsigned e = atomicAdd(&g_epoch, 0u);
        if (atomicAdd(&g_barcnt, 1u) == BB - 1u) {
            g_barcnt = 0u;
            __threadfence();
            atomicAdd(&g_epoch, 1u);
        } else {
            while (((volatile unsigned*)&g_epoch)[0] == e) { __nanosleep(64); }
        }
        __threadfence();
    }
    __syncthreads();
}

__device__ __forceinline__ int edge_at(const void* p, int idx, int is64) {
    return is64 ? ((const int*)p)[2 * idx] : ((const int*)p)[idx];
}

// ---------------- fused CSR build (1024 threads x 256 blocks, 2/SM) --------
__global__ __launch_bounds__(BT, 2) void k_build(const void* ei) {
    int t = threadIdx.x, b = blockIdx.x;
    int gid = b * BT + t;
    const int GSTR = BB * BT;

    if (gid == 0) {
        const long long* q = (const long long*)ei;
        int ok = 1;
        for (int j = 0; j < 256; j++) {
            long long v = q[j];
            if (v < 0 || v >= NN) { ok = 0; break; }
        }
        g_is64 = ok;
    }
    for (int i = gid; i < NN; i += GSTR) g_cnt[i] = 0;
    gsync();
    int is64 = g_is64;

    for (int e = gid; e < EE; e += GSTR) {
        int d = edge_at(ei, EE + e, is64);
        atomicAdd(&g_cnt[d], 1);
    }
    gsync();

    __shared__ int s[BT];
    __shared__ int sp[BB];
    int i = gid;
    int x = (i < NN) ? g_cnt[i] : 0;
    if (i < NN) g_dinv[i] = rsqrtf((float)(x + 1));
    s[t] = x;
    __syncthreads();
    for (int off = 1; off < BT; off <<= 1) {
        int v = (t >= off) ? s[t - off] : 0;
        __syncthreads();
        s[t] += v;
        __syncthreads();
    }
    int incl = s[t];
    if (t == BT - 1) g_part[b] = incl;
    gsync();

    if (t < BB) sp[t] = g_part[t];
    __syncthreads();
    for (int off = 1; off < BB; off <<= 1) {
        int v = 0;
        if (t < BB && t >= off) v = sp[t - off];
        __syncthreads();
        if (t < BB) sp[t] += v;
        __syncthreads();
    }
    int pre = (b > 0) ? sp[b - 1] : 0;
    if (i < NN) {
        int rs = pre + incl - x;
        g_rowstart[i] = rs;
        g_next[i] = rs;
    }
    if (gid == 0) g_rowstart[NN] = EE;
    gsync();

    for (int e = gid; e < EE; e += GSTR) {
        int sdx = edge_at(ei, e, is64);
        int dd  = edge_at(ei, EE + e, is64);
        int pos = atomicAdd(&g_next[dd], 1);
        g_edge[pos] = make_int2(sdx, __float_as_int(g_dinv[sdx]));
    }
}

// ---------------- W convert to fp16 (once per call) ----------------
__global__ void k_wconv(const float* __restrict__ w0, const float* __restrict__ w1,
                        const float* __restrict__ w2) {
    const float* W = (blockIdx.x == 0) ? w0 : ((blockIdx.x == 1) ? w1 : w2);
    __half* d1 = g_wh[blockIdx.x];
    for (int idx = threadIdx.x; idx < 16384; idx += 256) {
        d1[idx] = __float2half(W[idx]);
    }
}

// ------ persistent fp16 GEMM with W-fragments RESIDENT IN REGISTERS --------
// grid=296 (2 CTAs/SM), 256 threads = 8 warps (1m x 8n), warp tile 64x16.
// W staged to smem once -> ldmatrix into breg[8][4] -> smem reused for A.
// Steady state per k-step per warp: 4 LDSM4 (A) + 8 MMA, zero B traffic.
__global__ __launch_bounds__(256, 2) void k_gemm_p(
    const float* __restrict__ A, int layer, float* __restrict__ C,
    int tile0, int ntiles, int use_bn, int act)
{
    __shared__ unsigned char smb[32768];   // W stage (32K), then A tiles (16K)
    uint32_t sb = smem_u32(smb);

    int t = threadIdx.x, lane = t & 31, wid = t >> 5;
    int no = wid * 16;                     // warp col strip [no, no+16)
    int tend = tile0 + ntiles;

    int lr = (lane & 7) + (lane & 8);      // 0..15
    int lc = (lane >> 4) & 1;              // granule select

    // stage W fp16 swizzled (granule = 8 fp16 = 16 B)
    {
        const uint4* s1 = (const uint4*)g_wh[layer];
        for (int i = t; i < 2048; i += 256) {
            int row = i >> 4, g = i & 15;
            uint32_t off = (uint32_t)row * 256u + (uint32_t)((g ^ (row & 7)) << 4);
            *(uint4*)(smb + off) = s1[i];
        }
    }
    __syncthreads();

    // load this warp's B fragments into registers: breg[ks][4]
    uint32_t breg[8][4];
#pragma unroll
    for (int ks = 0; ks < 8; ks++) {
        uint32_t brow = (uint32_t)(ks * 16 + lr);
        uint32_t bg = (uint32_t)((no >> 3) + lc);
        uint32_t boff = brow * 256u + ((bg ^ (brow & 7u)) << 4);
        LDSM4T(breg[ks], sb + boff);
    }
    __syncthreads();   // frags in regs; smem free for A tiles

    for (int tile = tile0 + blockIdx.x; tile < tend; tile += gridDim.x) {
        int r0 = tile * 64;
        // stage A fp16 (64 x 128) with fused BN/act, swizzled, into smb[0..16K)
#pragma unroll
        for (int j = 0; j < 8; j++) {
            int i = t + j * 256;
            int row = i >> 5, col = (i & 31) * 4;
            int gr = r0 + row;
            float4 v = (gr < NN) ? *(const float4*)(A + (size_t)gr * DD + col)
                                 : make_float4(0.f, 0.f, 0.f, 0.f);
            if (use_bn) {
                v.x = v.x * g_scale[col + 0] + g_shift[col + 0];
                v.y = v.y * g_scale[col + 1] + g_shift[col + 1];
                v.z = v.z * g_scale[col + 2] + g_shift[col + 2];
                v.w = v.w * g_scale[col + 3] + g_shift[col + 3];
                if (act) {
                    v.x = v.x >= 0.f ? v.x : SLOPE * v.x;
                    v.y = v.y >= 0.f ? v.y : SLOPE * v.y;
                    v.z = v.z >= 0.f ? v.z : SLOPE * v.z;
                    v.w = v.w >= 0.f ? v.w : SLOPE * v.w;
                }
            }
            __half2 ha = __floats2half2_rn(v.x, v.y);
            __half2 hb = __floats2half2_rn(v.z, v.w);
            uint32_t off = (uint32_t)row * 256u
                         + (uint32_t)((((col >> 3) ^ (row & 7)) << 4))
                         + (uint32_t)((col & 4) << 1);
            uint2 u;
            u.x = *(uint32_t*)&ha; u.y = *(uint32_t*)&hb;
            *(uint2*)(smb + off) = u;
        }
        __syncthreads();

        float acc[4][2][4];
#pragma unroll
        for (int m = 0; m < 4; m++)
#pragma unroll
            for (int n = 0; n < 2; n++)
#pragma unroll
                for (int q = 0; q < 4; q++) acc[m][n][q] = 0.f;

#pragma unroll
        for (int ks = 0; ks < 8; ks++) {
            uint32_t ar[4][4];
#pragma unroll
            for (int m = 0; m < 4; m++) {
                uint32_t arow = (uint32_t)(m * 16 + lr);
                uint32_t ag = (uint32_t)(ks * 2 + lc);
                uint32_t aoff = arow * 256u + ((ag ^ (arow & 7u)) << 4);
                LDSM4(ar[m], sb + aoff);
            }
#pragma unroll
            for (int m = 0; m < 4; m++) {
                MMA16816H(acc[m][0], ar[m], breg[ks][0], breg[ks][1]);
                MMA16816H(acc[m][1], ar[m], breg[ks][2], breg[ks][3]);
            }
        }

        // epilogue: m16n8 lane mapping, direct float2 stores (NN % 16 == 0)
#pragma unroll
        for (int m = 0; m < 4; m++) {
            int rbm = r0 + m * 16;
            if (rbm + 16 <= NN) {
                int rr = rbm + (lane >> 2);
                int cc = no + (lane & 3) * 2;
#pragma unroll
                for (int n = 0; n < 2; n++) {
                    *(float2*)(C + (size_t)rr * DD + cc + n * 8) =
                        make_float2(acc[m][n][0], acc[m][n][1]);
                    *(float2*)(C + (size_t)(rr + 8) * DD + cc + n * 8) =
                        make_float2(acc[m][n][2], acc[m][n][3]);
                }
            }
        }
        __syncthreads();   // compute done before next iteration restages A
    }
}

// ---- aggregation: warp/node CSR gather + store-based BN-stats partials ----
__global__ __launch_bounds__(256, 7) void k_agg(
    const float* __restrict__ xw, float* __restrict__ outp,
    float* __restrict__ psum, float* __restrict__ psq)
{
    __shared__ float s1[8][128], s2[8][128];
    int t = threadIdx.x;
    int wid = t >> 5, lane = t & 31;
    int w = blockIdx.x * 8 + wid;
    float di = g_dinv[w];

    float4 acc = __ldg(reinterpret_cast<const float4*>(xw + (size_t)w * DD) + lane);
    float cself = di * di;
    acc.x *= cself; acc.y *= cself; acc.z *= cself; acc.w *= cself;

    int beg = g_rowstart[w], end = g_rowstart[w + 1];
    int i = beg;
    for (; i + 3 < end; i += 4) {
        int2 e0 = __ldg(&g_edge[i + 0]);
        int2 e1 = __ldg(&g_edge[i + 1]);
        int2 e2 = __ldg(&g_edge[i + 2]);
        int2 e3 = __ldg(&g_edge[i + 3]);
        float4 v0 = __ldg(reinterpret_cast<const float4*>(xw + (size_t)e0.x * DD) + lane);
        float4 v1 = __ldg(reinterpret_cast<const float4*>(xw + (size_t)e1.x * DD) + lane);
        float4 v2 = __ldg(reinterpret_cast<const float4*>(xw + (size_t)e2.x * DD) + lane);
        float4 v3 = __ldg(reinterpret_cast<const float4*>(xw + (size_t)e3.x * DD) + lane);
        float c0 = di * __int_as_float(e0.y);
        float c1 = di * __int_as_float(e1.y);
        float c2 = di * __int_as_float(e2.y);
        float c3 = di * __int_as_float(e3.y);
        acc.x = fmaf(c0, v0.x, acc.x); acc.y = fmaf(c0, v0.y, acc.y);
        acc.z = fmaf(c0, v0.z, acc.z); acc.w = fmaf(c0, v0.w, acc.w);
        acc.x = fmaf(c1, v1.x, acc.x); acc.y = fmaf(c1, v1.y, acc.y);
        acc.z = fmaf(c1, v1.z, acc.z); acc.w = fmaf(c1, v1.w, acc.w);
        acc.x = fmaf(c2, v2.x, acc.x); acc.y = fmaf(c2, v2.y, acc.y);
        acc.z = fmaf(c2, v2.z, acc.z); acc.w = fmaf(c2, v2.w, acc.w);
        acc.x = fmaf(c3, v3.x, acc.x); acc.y = fmaf(c3, v3.y, acc.y);
        acc.z = fmaf(c3, v3.z, acc.z); acc.w = fmaf(c3, v3.w, acc.w);
    }
    if (i < end) {
        int last = end - 1;
        int2 e0 = __ldg(&g_edge[i]);
        int2 e1 = __ldg(&g_edge[min(i + 1, last)]);
        int2 e2 = __ldg(&g_edge[min(i + 2, last)]);
        float4 v0 = __ldg(reinterpret_cast<const float4*>(xw + (size_t)e0.x * DD) + lane);
        float4 v1 = __ldg(reinterpret_cast<const float4*>(xw + (size_t)e1.x * DD) + lane);
        float4 v2 = __ldg(reinterpret_cast<const float4*>(xw + (size_t)e2.x * DD) + lane);
        float c0 = di * __int_as_float(e0.y);
        float c1 = (i + 1 < end) ? di * __int_as_float(e1.y) : 0.f;
        float c2 = (i + 2 < end) ? di * __int_as_float(e2.y) : 0.f;
        acc.x = fmaf(c0, v0.x, acc.x); acc.y = fmaf(c0, v0.y, acc.y);
        acc.z = fmaf(c0, v0.z, acc.z); acc.w = fmaf(c0, v0.w, acc.w);
        acc.x = fmaf(c1, v1.x, acc.x); acc.y = fmaf(c1, v1.y, acc.y);
        acc.z = fmaf(c1, v1.z, acc.z); acc.w = fmaf(c1, v1.w, acc.w);
        acc.x = fmaf(c2, v2.x, acc.x); acc.y = fmaf(c2, v2.y, acc.y);
        acc.z = fmaf(c2, v2.z, acc.z); acc.w = fmaf(c2, v2.w, acc.w);
    }
    reinterpret_cast<float4*>(outp + (size_t)w * DD)[lane] = acc;

    reinterpret_cast<float4*>(&s1[wid][0])[lane] = acc;
    reinterpret_cast<float4*>(&s2[wid][0])[lane] =
        make_float4(acc.x * acc.x, acc.y * acc.y, acc.z * acc.z, acc.w * acc.w);
    __syncthreads();
    if (t < 128) {
        float a = 0.f, b = 0.f;
#pragma unroll
        for (int ww = 0; ww < 8; ww++) { a += s1[ww][t]; b += s2[ww][t]; }
        psum[(size_t)blockIdx.x * DD + t] = a;
        psq [(size_t)blockIdx.x * DD + t] = b;
    }
}

// ---------------- BN stats finalize: block per feature ----------------
__global__ __launch_bounds__(256) void k_stats2(
    const float* __restrict__ gw, const float* __restrict__ be)
{
    __shared__ double r1[256], r2[256];
    int d = blockIdx.x;
    double s = 0.0, q = 0.0;
    for (int b = threadIdx.x; b < NBLK; b += 256) {
        s += (double)g_psum[(size_t)b * DD + d];
        q += (double)g_psq [(size_t)b * DD + d];
    }
    r1[threadIdx.x] = s; r2[threadIdx.x] = q;
    __syncthreads();
    for (int off = 128; off > 0; off >>= 1) {
        if (threadIdx.x < off) {
            r1[threadIdx.x] += r1[threadIdx.x + off];
            r2[threadIdx.x] += r2[threadIdx.x + off];
        }
        __syncthreads();
    }
    if (threadIdx.x == 0) {
        double mu = r1[0] / (double)NN;
        double var = r2[0] / (double)NN - mu * mu;
        float inv = (float)(1.0 / sqrt(var + 1e-5));
        float scl = gw[d] * inv;
        g_scale[d] = scl;
        g_shift[d] = be[d] - (float)mu * scl;
    }
}

// ---------------- final BN apply ----------------
__global__ void k_apply(float* __restrict__ h) {
    int idx = blockIdx.x * blockDim.x + threadIdx.x;
    if (idx < NN * DD / 4) {
        float4 v = reinterpret_cast<float4*>(h)[idx];
        int d = (idx & 31) * 4;
        v.x = v.x * g_scale[d + 0] + g_shift[d + 0];
        v.y = v.y * g_scale[d + 1] + g_shift[d + 1];
        v.z = v.z * g_scale[d + 2] + g_shift[d + 2];
        v.w = v.w * g_scale[d + 3] + g_shift[d + 3];
        reinterpret_cast<float4*>(h)[idx] = v;
    }
}

// ---------------- host launcher ----------------
extern "C" void kernel_launch(void* const* d_in, const int* in_sizes, int n_in,
                              void* d_out, int out_size) {
    const float* x   = (const float*)d_in[0];
    const void*  ei  = d_in[1];
    const float* w0  = (const float*)d_in[2];
    const float* g0  = (const float*)d_in[4];
    const float* be0 = (const float*)d_in[5];
    const float* w1  = (const float*)d_in[6];
    const float* g1  = (const float*)d_in[8];
    const float* be1 = (const float*)d_in[9];
    const float* w2  = (const float*)d_in[10];
    const float* g2  = (const float*)d_in[12];
    const float* be2 = (const float*)d_in[13];
    float* out = (float*)d_out;

    float *xw, *h, *ps, *pq;
    cudaGetSymbolAddress((void**)&xw, g_xw);
    cudaGetSymbolAddress((void**)&h,  g_h);
    cudaGetSymbolAddress((void**)&ps, g_psum);
    cudaGetSymbolAddress((void**)&pq, g_psq);

    const int TB = 256;
    const int GTILES = (NN + 63) / 64;     // 938
    const int GH = GTILES / 2;             // 469
    int gbP = (NN * DD / 4 + TB - 1) / TB;

    // layer 0 (launch #4 = GEMM second half -> ncu capture slot)
    k_build<<<BB, BT>>>(ei);                                              // 1
    k_wconv<<<3, TB>>>(w0, w1, w2);                                       // 2
    k_gemm_p<<<GEMM_GRID, TB>>>(x, 0, xw, 0, GH, 0, 0);                   // 3
    k_gemm_p<<<GEMM_GRID, TB>>>(x, 0, xw, GH, GTILES - GH, 0, 0);         // 4 <- profiled
    k_agg<<<NBLK, TB>>>(xw, h, ps, pq);                                   // 5
    k_stats2<<<DD, TB>>>(g0, be0);                                        // 6

    // layer 1 (BN0 + LeakyReLU fused into A staging)
    k_gemm_p<<<GEMM_GRID, TB>>>(h, 1, xw, 0, GTILES, 1, 1);
    k_agg<<<NBLK, TB>>>(xw, h, ps, pq);
    k_stats2<<<DD, TB>>>(g1, be1);

    // layer 2 (BN1 + LeakyReLU fused), final BN standalone
    k_gemm_p<<<GEMM_GRID, TB>>>(h, 2, xw, 0, GTILES, 1, 1);
    k_agg<<<NBLK, TB>>>(xw, out, ps, pq);
    k_stats2<<<DD, TB>>>(g2, be2);
    k_apply<<<gbP, TB>>>(out);
}

// round 16
// speedup vs baseline: 1.3946x; 1.0703x over previous
#include <cuda_runtime.h>
#include <cuda_fp16.h>
#include <cstdint>

#define NN 60000
#define EE 600000
#define DD 128
#define SLOPE 0.01f
#define BB 256            // build blocks (co-resident @ 2/SM)
#define BT 1024           // build threads
#define NBLK 7500         // agg stats partial blocks (60000/8)
#define GEMM_GRID 296     // persistent GEMM: 2 CTAs/SM

typedef unsigned long long ull;

// ---------------- device scratch (static, no allocation) ----------------
__device__ int   g_is64;
__device__ int   g_cnt[NN];
__device__ int   g_part[BB];
__device__ int   g_rowstart[NN + 1];
__device__ int   g_next[NN];
__device__ int2  g_edge[EE];
__device__ float g_dinv[NN];
__device__ __half g_xwh[(size_t)NN * DD];   // GEMM output, fp16 (gather side)
__device__ float g_h[(size_t)NN * DD];      // agg output, fp32
__device__ float g_psum[(size_t)NBLK * DD];
__device__ float g_psq[(size_t)NBLK * DD];
__device__ float g_scale[DD];
__device__ float g_shift[DD];
__device__ unsigned g_barcnt;
__device__ unsigned g_epoch;
// W as fp16, row-major [k][n]: [layer][128*128]
__device__ __align__(16) __half g_wh[3][16384];

// ---------------- mma.sync / ldmatrix primitives ----------------
__device__ __forceinline__ uint32_t smem_u32(const void* p) {
    return (uint32_t)__cvta_generic_to_shared(p);
}
#define LDSM4(r, addr)                                                         \
    asm volatile("ldmatrix.sync.aligned.m8n8.x4.shared.b16 {%0,%1,%2,%3}, [%4];" \
                 : "=r"((r)[0]), "=r"((r)[1]), "=r"((r)[2]), "=r"((r)[3])      \
                 : "r"(addr))
#define LDSM4T(r, addr)                                                        \
    asm volatile("ldmatrix.sync.aligned.m8n8.x4.trans.shared.b16 {%0,%1,%2,%3}, [%4];" \
                 : "=r"((r)[0]), "=r"((r)[1]), "=r"((r)[2]), "=r"((r)[3])      \
                 : "r"(addr))
#define MMA16816H(d, a, b0, b1)                                                \
    asm volatile("mma.sync.aligned.m16n8k16.row.col.f32.f16.f16.f32 "          \
                 "{%0,%1,%2,%3},{%4,%5,%6,%7},{%8,%9},{%0,%1,%2,%3};"          \
                 : "+f"((d)[0]), "+f"((d)[1]), "+f"((d)[2]), "+f"((d)[3])      \
                 : "r"((a)[0]), "r"((a)[1]), "r"((a)[2]), "r"((a)[3]),         \
                   "r"(b0), "r"(b1))

// ---------------- global spin barrier (BB blocks resident) -----------------
__device__ __forceinline__ void gsync() {
    __syncthreads();
    if (threadIdx.x == 0) {
        __threadfence();
        unsigned e = atomicAdd(&g_epoch, 0u);
        if (atomicAdd(&g_barcnt, 1u) == BB - 1u) {
            g_barcnt = 0u;
            __threadfence();
            atomicAdd(&g_epoch, 1u);
        } else {
            while (((volatile unsigned*)&g_epoch)[0] == e) { __nanosleep(64); }
        }
        __threadfence();
    }
    __syncthreads();
}

__device__ __forceinline__ int edge_at(const void* p, int idx, int is64) {
    return is64 ? ((const int*)p)[2 * idx] : ((const int*)p)[idx];
}

// ---------------- fused CSR build (1024 threads x 256 blocks, 2/SM) --------
__global__ __launch_bounds__(BT, 2) void k_build(const void* ei) {
    int t = threadIdx.x, b = blockIdx.x;
    int gid = b * BT + t;
    const int GSTR = BB * BT;

    if (gid == 0) {
        const long long* q = (const long long*)ei;
        int ok = 1;
        for (int j = 0; j < 256; j++) {
            long long v = q[j];
            if (v < 0 || v >= NN) { ok = 0; break; }
        }
        g_is64 = ok;
    }
    for (int i = gid; i < NN; i += GSTR) g_cnt[i] = 0;
    gsync();
    int is64 = g_is64;

    for (int e = gid; e < EE; e += GSTR) {
        int d = edge_at(ei, EE + e, is64);
        atomicAdd(&g_cnt[d], 1);
    }
    gsync();

    __shared__ int s[BT];
    __shared__ int sp[BB];
    int i = gid;
    int x = (i < NN) ? g_cnt[i] : 0;
    if (i < NN) g_dinv[i] = rsqrtf((float)(x + 1));
    s[t] = x;
    __syncthreads();
    for (int off = 1; off < BT; off <<= 1) {
        int v = (t >= off) ? s[t - off] : 0;
        __syncthreads();
        s[t] += v;
        __syncthreads();
    }
    int incl = s[t];
    if (t == BT - 1) g_part[b] = incl;
    gsync();

    if (t < BB) sp[t] = g_part[t];
    __syncthreads();
    for (int off = 1; off < BB; off <<= 1) {
        int v = 0;
        if (t < BB && t >= off) v = sp[t - off];
        __syncthreads();
        if (t < BB) sp[t] += v;
        __syncthreads();
    }
    int pre = (b > 0) ? sp[b - 1] : 0;
    if (i < NN) {
        int rs = pre + incl - x;
        g_rowstart[i] = rs;
        g_next[i] = rs;
    }
    if (gid == 0) g_rowstart[NN] = EE;
    gsync();

    for (int e = gid; e < EE; e += GSTR) {
        int sdx = edge_at(ei, e, is64);
        int dd  = edge_at(ei, EE + e, is64);
        int pos = atomicAdd(&g_next[dd], 1);
        g_edge[pos] = make_int2(sdx, __float_as_int(g_dinv[sdx]));
    }
}

// ---------------- W convert to fp16 (once per call) ----------------
__global__ void k_wconv(const float* __restrict__ w0, const float* __restrict__ w1,
                        const float* __restrict__ w2) {
    const float* W = (blockIdx.x == 0) ? w0 : ((blockIdx.x == 1) ? w1 : w2);
    __half* d1 = g_wh[blockIdx.x];
    for (int idx = threadIdx.x; idx < 16384; idx += 256) {
        d1[idx] = __float2half(W[idx]);
    }
}

// ------ persistent fp16 GEMM, W-fragments in registers, fp16 C output ------
// grid=296 (2 CTAs/SM), 256 threads = 8 warps (1m x 8n), warp tile 64x16.
__global__ __launch_bounds__(256, 2) void k_gemm_p(
    const float* __restrict__ A, int layer, __half* __restrict__ C,
    int use_bn, int act)
{
    __shared__ unsigned char smb[32768];   // W stage (32K), then A tiles (16K)
    uint32_t sb = smem_u32(smb);

    int t = threadIdx.x, lane = t & 31, wid = t >> 5;
    int no = wid * 16;                     // warp col strip [no, no+16)
    const int GT = (NN + 63) / 64;         // 938 tiles

    int lr = (lane & 7) + (lane & 8);      // 0..15
    int lc = (lane >> 4) & 1;              // granule select

    // stage W fp16 swizzled (granule = 8 fp16 = 16 B)
    {
        const uint4* s1 = (const uint4*)g_wh[layer];
        for (int i = t; i < 2048; i += 256) {
            int row = i >> 4, g = i & 15;
            uint32_t off = (uint32_t)row * 256u + (uint32_t)((g ^ (row & 7)) << 4);
            *(uint4*)(smb + off) = s1[i];
        }
    }
    __syncthreads();

    // load this warp's B fragments into registers: breg[ks][4]
    uint32_t breg[8][4];
#pragma unroll
    for (int ks = 0; ks < 8; ks++) {
        uint32_t brow = (uint32_t)(ks * 16 + lr);
        uint32_t bg = (uint32_t)((no >> 3) + lc);
        uint32_t boff = brow * 256u + ((bg ^ (brow & 7u)) << 4);
        LDSM4T(breg[ks], sb + boff);
    }
    __syncthreads();   // frags in regs; smem free for A tiles

    for (int tile = blockIdx.x; tile < GT; tile += gridDim.x) {
        int r0 = tile * 64;
        // stage A fp16 (64 x 128) with fused BN/act, swizzled
#pragma unroll
        for (int j = 0; j < 8; j++) {
            int i = t + j * 256;
            int row = i >> 5, col = (i & 31) * 4;
            int gr = r0 + row;
            float4 v = (gr < NN) ? *(const float4*)(A + (size_t)gr * DD + col)
                                 : make_float4(0.f, 0.f, 0.f, 0.f);
            if (use_bn) {
                v.x = v.x * g_scale[col + 0] + g_shift[col + 0];
                v.y = v.y * g_scale[col + 1] + g_shift[col + 1];
                v.z = v.z * g_scale[col + 2] + g_shift[col + 2];
                v.w = v.w * g_scale[col + 3] + g_shift[col + 3];
                if (act) {
                    v.x = v.x >= 0.f ? v.x : SLOPE * v.x;
                    v.y = v.y >= 0.f ? v.y : SLOPE * v.y;
                    v.z = v.z >= 0.f ? v.z : SLOPE * v.z;
                    v.w = v.w >= 0.f ? v.w : SLOPE * v.w;
                }
            }
            __half2 ha = __floats2half2_rn(v.x, v.y);
            __half2 hb = __floats2half2_rn(v.z, v.w);
            uint32_t off = (uint32_t)row * 256u
                         + (uint32_t)((((col >> 3) ^ (row & 7)) << 4))
                         + (uint32_t)((col & 4) << 1);
            uint2 u;
            u.x = *(uint32_t*)&ha; u.y = *(uint32_t*)&hb;
            *(uint2*)(smb + off) = u;
        }
        __syncthreads();

        float acc[4][2][4];
#pragma unroll
        for (int m = 0; m < 4; m++)
#pragma unroll
            for (int n = 0; n < 2; n++)
#pragma unroll
                for (int q = 0; q < 4; q++) acc[m][n][q] = 0.f;

#pragma unroll
        for (int ks = 0; ks < 8; ks++) {
            uint32_t ar[4][4];
#pragma unroll
            for (int m = 0; m < 4; m++) {
                uint32_t arow = (uint32_t)(m * 16 + lr);
                uint32_t ag = (uint32_t)(ks * 2 + lc);
                uint32_t aoff = arow * 256u + ((ag ^ (arow & 7u)) << 4);
                LDSM4(ar[m], sb + aoff);
            }
#pragma unroll
            for (int m = 0; m < 4; m++) {
                MMA16816H(acc[m][0], ar[m], breg[ks][0], breg[ks][1]);
                MMA16816H(acc[m][1], ar[m], breg[ks][2], breg[ks][3]);
            }
        }

        // epilogue: fp16 stores (m16n8 lane mapping), NN % 16 == 0
#pragma unroll
        for (int m = 0; m < 4; m++) {
            int rbm = r0 + m * 16;
            if (rbm + 16 <= NN) {
                int rr = rbm + (lane >> 2);
                int cc = no + (lane & 3) * 2;
#pragma unroll
                for (int n = 0; n < 2; n++) {
                    __half2 h0 = __floats2half2_rn(acc[m][n][0], acc[m][n][1]);
                    __half2 h1 = __floats2half2_rn(acc[m][n][2], acc[m][n][3]);
                    *(__half2*)(C + (size_t)rr * DD + cc + n * 8) = h0;
                    *(__half2*)(C + (size_t)(rr + 8) * DD + cc + n * 8) = h1;
                }
            }
        }
        __syncthreads();   // compute done before next iteration restages A
    }
}

// ---- aggregation: warp/node CSR gather of fp16 rows + fused BN stats ------
__device__ __forceinline__ void acc4(float4& a, float c, uint2 u) {
    float2 f0 = __half22float2(*(__half2*)&u.x);
    float2 f1 = __half22float2(*(__half2*)&u.y);
    a.x = fmaf(c, f0.x, a.x); a.y = fmaf(c, f0.y, a.y);
    a.z = fmaf(c, f1.x, a.z); a.w = fmaf(c, f1.y, a.w);
}

__global__ __launch_bounds__(256, 7) void k_agg(
    const __half* __restrict__ xw, float* __restrict__ outp,
    float* __restrict__ psum, float* __restrict__ psq)
{
    __shared__ float s1[8][128], s2[8][128];
    int t = threadIdx.x;
    int wid = t >> 5, lane = t & 31;
    int w = blockIdx.x * 8 + wid;
    float di = g_dinv[w];

    // self loop (coef = dinv^2)
    uint2 us = __ldg((const uint2*)(xw + (size_t)w * DD) + lane);
    float4 acc = make_float4(0.f, 0.f, 0.f, 0.f);
    acc4(acc, di * di, us);

    int beg = g_rowstart[w], end = g_rowstart[w + 1];
    int i = beg;
    for (; i + 3 < end; i += 4) {
        int2 e0 = __ldg(&g_edge[i + 0]);
        int2 e1 = __ldg(&g_edge[i + 1]);
        int2 e2 = __ldg(&g_edge[i + 2]);
        int2 e3 = __ldg(&g_edge[i + 3]);
        uint2 v0 = __ldg((const uint2*)(xw + (size_t)e0.x * DD) + lane);
        uint2 v1 = __ldg((const uint2*)(xw + (size_t)e1.x * DD) + lane);
        uint2 v2 = __ldg((const uint2*)(xw + (size_t)e2.x * DD) + lane);
        uint2 v3 = __ldg((const uint2*)(xw + (size_t)e3.x * DD) + lane);
        acc4(acc, di * __int_as_float(e0.y), v0);
        acc4(acc, di * __int_as_float(e1.y), v1);
        acc4(acc, di * __int_as_float(e2.y), v2);
        acc4(acc, di * __int_as_float(e3.y), v3);
    }
    if (i < end) {
        int last = end - 1;
        int2 e0 = __ldg(&g_edge[i]);
        int2 e1 = __ldg(&g_edge[min(i + 1, last)]);
        int2 e2 = __ldg(&g_edge[min(i + 2, last)]);
        uint2 v0 = __ldg((const uint2*)(xw + (size_t)e0.x * DD) + lane);
        uint2 v1 = __ldg((const uint2*)(xw + (size_t)e1.x * DD) + lane);
        uint2 v2 = __ldg((const uint2*)(xw + (size_t)e2.x * DD) + lane);
        float c1 = (i + 1 < end) ? di * __int_as_float(e1.y) : 0.f;
        float c2 = (i + 2 < end) ? di * __int_as_float(e2.y) : 0.f;
        acc4(acc, di * __int_as_float(e0.y), v0);
        acc4(acc, c1, v1);
        acc4(acc, c2, v2);
    }
    reinterpret_cast<float4*>(outp + (size_t)w * DD)[lane] = acc;

    reinterpret_cast<float4*>(&s1[wid][0])[lane] = acc;
    reinterpret_cast<float4*>(&s2[wid][0])[lane] =
        make_float4(acc.x * acc.x, acc.y * acc.y, acc.z * acc.z, acc.w * acc.w);
    __syncthreads();
    if (t < 128) {
        float a = 0.f, b = 0.f;
#pragma unroll
        for (int ww = 0; ww < 8; ww++) { a += s1[ww][t]; b += s2[ww][t]; }
        psum[(size_t)blockIdx.x * DD + t] = a;
        psq [(size_t)blockIdx.x * DD + t] = b;
    }
}

// ---------------- BN stats finalize: block per feature ----------------
__global__ __launch_bounds__(256) void k_stats2(
    const float* __restrict__ gw, const float* __restrict__ be)
{
    __shared__ double r1[256], r2[256];
    int d = blockIdx.x;
    double s = 0.0, q = 0.0;
    for (int b = threadIdx.x; b < NBLK; b += 256) {
        s += (double)g_psum[(size_t)b * DD + d];
        q += (double)g_psq [(size_t)b * DD + d];
    }
    r1[threadIdx.x] = s; r2[threadIdx.x] = q;
    __syncthreads();
    for (int off = 128; off > 0; off >>= 1) {
        if (threadIdx.x < off) {
            r1[threadIdx.x] += r1[threadIdx.x + off];
            r2[threadIdx.x] += r2[threadIdx.x + off];
        }
        __syncthreads();
    }
    if (threadIdx.x == 0) {
        double mu = r1[0] / (double)NN;
        double var = r2[0] / (double)NN - mu * mu;
        float inv = (float)(1.0 / sqrt(var + 1e-5));
        float scl = gw[d] * inv;
        g_scale[d] = scl;
        g_shift[d] = be[d] - (float)mu * scl;
    }
}

// ---------------- final BN apply ----------------
__global__ void k_apply(float* __restrict__ h) {
    int idx = blockIdx.x * blockDim.x + threadIdx.x;
    if (idx < NN * DD / 4) {
        float4 v = reinterpret_cast<float4*>(h)[idx];
        int d = (idx & 31) * 4;
        v.x = v.x * g_scale[d + 0] + g_shift[d + 0];
        v.y = v.y * g_scale[d + 1] + g_shift[d + 1];
        v.z = v.z * g_scale[d + 2] + g_shift[d + 2];
        v.w = v.w * g_scale[d + 3] + g_shift[d + 3];
        reinterpret_cast<float4*>(h)[idx] = v;
    }
}

// ---------------- host launcher ----------------
extern "C" void kernel_launch(void* const* d_in, const int* in_sizes, int n_in,
                              void* d_out, int out_size) {
    const float* x   = (const float*)d_in[0];
    const void*  ei  = d_in[1];
    const float* w0  = (const float*)d_in[2];
    const float* g0  = (const float*)d_in[4];
    const float* be0 = (const float*)d_in[5];
    const float* w1  = (const float*)d_in[6];
    const float* g1  = (const float*)d_in[8];
    const float* be1 = (const float*)d_in[9];
    const float* w2  = (const float*)d_in[10];
    const float* g2  = (const float*)d_in[12];
    const float* be2 = (const float*)d_in[13];
    float* out = (float*)d_out;

    __half* xwh;
    float *h, *ps, *pq;
    cudaGetSymbolAddress((void**)&xwh, g_xwh);
    cudaGetSymbolAddress((void**)&h,   g_h);
    cudaGetSymbolAddress((void**)&ps,  g_psum);
    cudaGetSymbolAddress((void**)&pq,  g_psq);

    const int TB = 256;
    int gbP = (NN * DD / 4 + TB - 1) / TB;

    // layer 0 (launch #4 = agg with fp16 gather -> ncu capture slot)
    k_build<<<BB, BT>>>(ei);                               // 1
    k_wconv<<<3, TB>>>(w0, w1, w2);                        // 2
    k_gemm_p<<<GEMM_GRID, TB>>>(x, 0, xwh, 0, 0);          // 3
    k_agg<<<NBLK, TB>>>(xwh, h, ps, pq);                   // 4 <- profiled
    k_stats2<<<DD, TB>>>(g0, be0);                         // 5

    // layer 1 (BN0 + LeakyReLU fused into A staging)
    k_gemm_p<<<GEMM_GRID, TB>>>(h, 1, xwh, 1, 1);
    k_agg<<<NBLK, TB>>>(xwh, h, ps, pq);
    k_stats2<<<DD, TB>>>(g1, be1);

    // layer 2 (BN1 + LeakyReLU fused), final BN standalone
    k_gemm_p<<<GEMM_GRID, TB>>>(h, 2, xwh, 1, 1);
    k_agg<<<NBLK, TB>>>(xwh, out, ps, pq);
    k_stats2<<<DD, TB>>>(g2, be2);
    k_apply<<<gbP, TB>>>(out);
}